// round 1
// baseline (speedup 1.0000x reference)
#include <cuda_runtime.h>
#include <math.h>
#include <math_constants.h>

#define B_  4
#define S_  2048
#define D_  1024
#define H_  16
#define DH_ 64
#define SCALE_ 0.125f

// Scratch (allocation-free rule: __device__ globals)
__device__ float g_q[(size_t)B_*H_*S_*DH_];
__device__ float g_k[(size_t)B_*H_*S_*DH_];
__device__ float g_v[(size_t)B_*H_*S_*DH_];
__device__ float g_attn[(size_t)B_*S_*D_];
__device__ float g_freqs[32];

// ---------------------------------------------------------------------------
// Freq prep: f[i] = 10000^(-i/32), computed in double -> correctly rounded f32
// ---------------------------------------------------------------------------
__global__ void prep_freqs_kernel() {
    int i = threadIdx.x;
    if (i < 32) {
        g_freqs[i] = (float)exp(-(double)i * (9.210340371976184 / 32.0));
    }
}

// ---------------------------------------------------------------------------
// GEMM: C[M,N] = A[M,K] @ W[N,K]^T + bias[N]
// MODE 0: A = x, scatter-store into g_q/g_k/g_v  (n -> (i3, h, d), m -> (b, s))
// MODE 1: A = g_attn, plain store to Cext (d_out)
// BM=BN=128, BK=16, 256 threads, 8x8 per thread (split 4+4 fragments)
// ---------------------------------------------------------------------------
template<int MODE>
__global__ __launch_bounds__(256) void gemm_kernel(
    const float* __restrict__ Aext, const float* __restrict__ W,
    const float* __restrict__ bias, float* __restrict__ Cext,
    int N, int K)
{
    const float* A = (MODE == 1) ? g_attn : Aext;
    const int m0 = blockIdx.y * 128;
    const int n0 = blockIdx.x * 128;
    const int tx = threadIdx.x, ty = threadIdx.y;
    const int tid = ty * 16 + tx;

    __shared__ float As[16][132];
    __shared__ float Bs[16][132];

    float acc[8][8];
#pragma unroll
    for (int i = 0; i < 8; i++)
#pragma unroll
        for (int j = 0; j < 8; j++) acc[i][j] = 0.0f;

    for (int k0 = 0; k0 < K; k0 += 16) {
#pragma unroll
        for (int i = 0; i < 2; i++) {
            int f  = tid + i * 256;
            int r  = f >> 2;
            int kq = f & 3;
            float4 av = *(const float4*)(A + (size_t)(m0 + r) * K + k0 + kq * 4);
            As[kq * 4 + 0][r] = av.x;
            As[kq * 4 + 1][r] = av.y;
            As[kq * 4 + 2][r] = av.z;
            As[kq * 4 + 3][r] = av.w;
            float4 bv = *(const float4*)(W + (size_t)(n0 + r) * K + k0 + kq * 4);
            Bs[kq * 4 + 0][r] = bv.x;
            Bs[kq * 4 + 1][r] = bv.y;
            Bs[kq * 4 + 2][r] = bv.z;
            Bs[kq * 4 + 3][r] = bv.w;
        }
        __syncthreads();
#pragma unroll
        for (int kk = 0; kk < 16; kk++) {
            float a[8], b[8];
            *(float4*)(a)     = *(const float4*)&As[kk][ty * 4];
            *(float4*)(a + 4) = *(const float4*)&As[kk][64 + ty * 4];
            *(float4*)(b)     = *(const float4*)&Bs[kk][tx * 4];
            *(float4*)(b + 4) = *(const float4*)&Bs[kk][64 + tx * 4];
#pragma unroll
            for (int mi = 0; mi < 8; mi++)
#pragma unroll
                for (int ni = 0; ni < 8; ni++)
                    acc[mi][ni] += a[mi] * b[ni];
        }
        __syncthreads();
    }

    // Epilogue
#pragma unroll
    for (int mi = 0; mi < 8; mi++) {
        int rm = m0 + ((mi < 4) ? (ty * 4 + mi) : (64 + ty * 4 + mi - 4));
#pragma unroll
        for (int nh = 0; nh < 2; nh++) {
            int cn = n0 + nh * 64 + tx * 4;
            float4 bv = *(const float4*)(bias + cn);
            float4 o;
            o.x = acc[mi][nh * 4 + 0] + bv.x;
            o.y = acc[mi][nh * 4 + 1] + bv.y;
            o.z = acc[mi][nh * 4 + 2] + bv.z;
            o.w = acc[mi][nh * 4 + 3] + bv.w;
            if (MODE == 1) {
                *(float4*)(Cext + (size_t)rm * N + cn) = o;
            } else {
                int i3  = cn >> 10;
                int rem = cn & 1023;
                int h   = rem >> 6;
                int d   = rem & 63;
                int b_  = rm >> 11;
                int s   = rm & 2047;
                float* base = (i3 == 0) ? g_q : (i3 == 1) ? g_k : g_v;
                *(float4*)(base + ((size_t)((b_ * H_ + h) * S_) + s) * DH_ + d) = o;
            }
        }
    }
}

// ---------------------------------------------------------------------------
// RoPE in-place on g_q, g_k. One thread per (b,h,s,d2<32), handles d2 & d2+32.
// ---------------------------------------------------------------------------
__global__ __launch_bounds__(256) void rope_kernel(const int* __restrict__ p) {
    int idx = blockIdx.x * 256 + threadIdx.x;   // 4*16*2048*32 = 4194304 total
    int d2 = idx & 31;
    int s  = (idx >> 5) & 2047;
    int h  = (idx >> 16) & 15;
    int b  = idx >> 20;

    float f  = g_freqs[d2];
    float th = (float)p[b * S_ + s] * f;
    float sn, cs;
    sincosf(th, &sn, &cs);

    size_t base = ((size_t)((b * H_ + h) * S_) + s) * DH_;
    float q1 = g_q[base + d2], q2 = g_q[base + d2 + 32];
    g_q[base + d2]      = q1 * cs + q2 * sn;
    g_q[base + d2 + 32] = q2 * cs - q1 * sn;
    float k1 = g_k[base + d2], k2 = g_k[base + d2 + 32];
    g_k[base + d2]      = k1 * cs + k2 * sn;
    g_k[base + d2 + 32] = k2 * cs - k1 * sn;
}

// ---------------------------------------------------------------------------
// Flash attention: grid (S/64, H, B), block (16,16).
// Qs natural [qr][d] (scaled by 0.125 on load), KPs XOR-swizzled (K tile then
// reused for P), Vs natural. Online softmax, 4x4 fragments per thread.
// Output written as [B, S, H*Dh] directly into g_attn.
// ---------------------------------------------------------------------------
#define KSW(r, c) ((r) * 64 + ((c) ^ ((r) & 31)))

__global__ __launch_bounds__(256) void flash_kernel() {
    const int tx = threadIdx.x, ty = threadIdx.y;
    const int tid = ty * 16 + tx;
    const int qb = blockIdx.x * 64;
    const int h  = blockIdx.y;
    const int b  = blockIdx.z;
    const size_t bh = (size_t)(b * H_ + h) * S_ * DH_;
    const float* Qg = g_q + bh;
    const float* Kg = g_k + bh;
    const float* Vg = g_v + bh;

    __shared__ float Qs[64 * 64];
    __shared__ float KPs[64 * 64];
    __shared__ float Vs[64 * 64];

    // Load Q tile (scale folded in; 0.125 is exact)
#pragma unroll
    for (int i = 0; i < 4; i++) {
        int f = tid + i * 256;
        int r = f >> 4, c4 = f & 15;
        float4 v = *(const float4*)(Qg + (size_t)(qb + r) * DH_ + c4 * 4);
        v.x *= SCALE_; v.y *= SCALE_; v.z *= SCALE_; v.w *= SCALE_;
        *(float4*)&Qs[r * 64 + c4 * 4] = v;
    }

    float m[4], l[4], acc[4][4];
#pragma unroll
    for (int qi = 0; qi < 4; qi++) {
        m[qi] = -CUDART_INF_F;
        l[qi] = 0.0f;
#pragma unroll
        for (int dc = 0; dc < 4; dc++) acc[qi][dc] = 0.0f;
    }

    for (int kt = 0; kt < S_; kt += 64) {
        __syncthreads();   // previous PV done (and Q load visible on iter 0)
        // Load K (swizzled) + V (natural)
#pragma unroll
        for (int i = 0; i < 4; i++) {
            int f = tid + i * 256;
            int r = f >> 4, c4 = f & 15;
            int cb = c4 * 4;
            float4 kv = *(const float4*)(Kg + (size_t)(kt + r) * DH_ + cb);
            KPs[KSW(r, cb + 0)] = kv.x;
            KPs[KSW(r, cb + 1)] = kv.y;
            KPs[KSW(r, cb + 2)] = kv.z;
            KPs[KSW(r, cb + 3)] = kv.w;
            *(float4*)&Vs[r * 64 + cb] =
                *(const float4*)(Vg + (size_t)(kt + r) * DH_ + cb);
        }
        __syncthreads();

        // S = Q K^T (Q pre-scaled)
        float sf[4][4];
#pragma unroll
        for (int qi = 0; qi < 4; qi++)
#pragma unroll
            for (int kj = 0; kj < 4; kj++) sf[qi][kj] = 0.0f;

#pragma unroll 8
        for (int d = 0; d < 64; d++) {
            float qv[4], kv[4];
#pragma unroll
            for (int qi = 0; qi < 4; qi++)
                qv[qi] = Qs[(ty * 4 + qi) * 64 + d];
#pragma unroll
            for (int kj = 0; kj < 4; kj++) {
                int kc = tx * 4 + kj;
                kv[kj] = KPs[KSW(kc, d)];
            }
#pragma unroll
            for (int qi = 0; qi < 4; qi++)
#pragma unroll
                for (int kj = 0; kj < 4; kj++)
                    sf[qi][kj] += qv[qi] * kv[kj];
        }

        // Online softmax (row reductions over the 16-lane tx group)
#pragma unroll
        for (int qi = 0; qi < 4; qi++) {
            float mx = fmaxf(fmaxf(sf[qi][0], sf[qi][1]),
                             fmaxf(sf[qi][2], sf[qi][3]));
#pragma unroll
            for (int off = 8; off >= 1; off >>= 1)
                mx = fmaxf(mx, __shfl_xor_sync(0xffffffffu, mx, off));
            float mnew = fmaxf(m[qi], mx);
            float corr = __expf(m[qi] - mnew);
            float sum = 0.0f;
#pragma unroll
            for (int kj = 0; kj < 4; kj++) {
                float pv = __expf(sf[qi][kj] - mnew);
                sf[qi][kj] = pv;
                sum += pv;
            }
#pragma unroll
            for (int off = 8; off >= 1; off >>= 1)
                sum += __shfl_xor_sync(0xffffffffu, sum, off);
            l[qi] = l[qi] * corr + sum;
            m[qi] = mnew;
#pragma unroll
            for (int dc = 0; dc < 4; dc++) acc[qi][dc] *= corr;
        }

        __syncthreads();   // everyone done reading K from KPs
        // Store P into KPs
#pragma unroll
        for (int qi = 0; qi < 4; qi++)
#pragma unroll
            for (int kj = 0; kj < 4; kj++) {
                int kc = tx * 4 + kj;
                KPs[KSW(kc, ty * 4 + qi)] = sf[qi][kj];
            }
        __syncthreads();

        // O += P @ V
#pragma unroll 8
        for (int j = 0; j < 64; j++) {
            float pf[4], vf[4];
#pragma unroll
            for (int qi = 0; qi < 4; qi++)
                pf[qi] = KPs[KSW(j, ty * 4 + qi)];
#pragma unroll
            for (int dc = 0; dc < 4; dc++)
                vf[dc] = Vs[j * 64 + tx * 4 + dc];
#pragma unroll
            for (int qi = 0; qi < 4; qi++)
#pragma unroll
                for (int dc = 0; dc < 4; dc++)
                    acc[qi][dc] += pf[qi] * vf[dc];
        }
    }

    // Normalize and store into g_attn [B, S, D] (column block h*64)
#pragma unroll
    for (int qi = 0; qi < 4; qi++) {
        float inv = 1.0f / l[qi];
        int s = qb + ty * 4 + qi;
        float4 o;
        o.x = acc[qi][0] * inv;
        o.y = acc[qi][1] * inv;
        o.z = acc[qi][2] * inv;
        o.w = acc[qi][3] * inv;
        *(float4*)(g_attn + ((size_t)(b * S_ + s)) * D_ + h * 64 + tx * 4) = o;
    }
}

// ---------------------------------------------------------------------------
// Launch
// ---------------------------------------------------------------------------
extern "C" void kernel_launch(void* const* d_in, const int* in_sizes, int n_in,
                              void* d_out, int out_size) {
    const float* x      = (const float*)d_in[0];
    const int*   p      = (const int*)d_in[1];
    const float* Wqkv_w = (const float*)d_in[2];
    const float* Wqkv_b = (const float*)d_in[3];
    const float* Wo_w   = (const float*)d_in[4];
    const float* Wo_b   = (const float*)d_in[5];
    float* out = (float*)d_out;

    dim3 blk(16, 16);

    // 1. QKV projection + scatter into g_q/g_k/g_v
    gemm_kernel<0><<<dim3(3 * D_ / 128, (B_ * S_) / 128), blk>>>(
        x, Wqkv_w, Wqkv_b, nullptr, 3 * D_, D_);

    // 2. RoPE
    prep_freqs_kernel<<<1, 32>>>();
    rope_kernel<<<(B_ * H_ * S_ * 32) / 256, 256>>>(p);

    // 3. Flash attention -> g_attn
    flash_kernel<<<dim3(S_ / 64, H_, B_), blk>>>();

    // 4. Output projection
    gemm_kernel<1><<<dim3(D_ / 128, (B_ * S_) / 128), blk>>>(
        nullptr, Wo_w, Wo_b, out, D_, D_);
}

// round 2
// speedup vs baseline: 1.2599x; 1.2599x over previous
#include <cuda_runtime.h>
#include <math.h>
#include <math_constants.h>

#define B_  4
#define S_  2048
#define D_  1024
#define H_  16
#define DH_ 64
#define SCALE_ 0.125f

// Scratch (allocation-free rule: __device__ globals)
__device__ float g_q[(size_t)B_*H_*S_*DH_];
__device__ float g_k[(size_t)B_*H_*S_*DH_];
__device__ float g_v[(size_t)B_*H_*S_*DH_];
__device__ float g_attn[(size_t)B_*S_*D_];
__device__ float g_freqs[32];

// ---------------------------------------------------------------------------
// Freq prep: f[i] = 10000^(-i/32), computed in double -> correctly rounded f32
// ---------------------------------------------------------------------------
__global__ void prep_freqs_kernel() {
    int i = threadIdx.x;
    if (i < 32) {
        g_freqs[i] = (float)exp(-(double)i * (9.210340371976184 / 32.0));
    }
}

// ---------------------------------------------------------------------------
// GEMM: C[M,N] = A[M,K] @ W[N,K]^T + bias[N]
// MODE 0: A = x, scatter-store into g_q/g_k/g_v  (n -> (i3, h, d), m -> (b, s))
// MODE 1: A = g_attn, plain store to Cext (d_out)
// BM=BN=128, BK=16, 256 threads, 8x8 per thread (split 4+4 fragments)
// ---------------------------------------------------------------------------
template<int MODE>
__global__ __launch_bounds__(256) void gemm_kernel(
    const float* __restrict__ Aext, const float* __restrict__ W,
    const float* __restrict__ bias, float* __restrict__ Cext,
    int N, int K)
{
    const float* A = (MODE == 1) ? g_attn : Aext;
    const int m0 = blockIdx.y * 128;
    const int n0 = blockIdx.x * 128;
    const int tx = threadIdx.x, ty = threadIdx.y;
    const int tid = ty * 16 + tx;

    __shared__ float As[16][132];
    __shared__ float Bs[16][132];

    float acc[8][8];
#pragma unroll
    for (int i = 0; i < 8; i++)
#pragma unroll
        for (int j = 0; j < 8; j++) acc[i][j] = 0.0f;

    for (int k0 = 0; k0 < K; k0 += 16) {
#pragma unroll
        for (int i = 0; i < 2; i++) {
            int f  = tid + i * 256;
            int r  = f >> 2;
            int kq = f & 3;
            float4 av = *(const float4*)(A + (size_t)(m0 + r) * K + k0 + kq * 4);
            As[kq * 4 + 0][r] = av.x;
            As[kq * 4 + 1][r] = av.y;
            As[kq * 4 + 2][r] = av.z;
            As[kq * 4 + 3][r] = av.w;
            float4 bv = *(const float4*)(W + (size_t)(n0 + r) * K + k0 + kq * 4);
            Bs[kq * 4 + 0][r] = bv.x;
            Bs[kq * 4 + 1][r] = bv.y;
            Bs[kq * 4 + 2][r] = bv.z;
            Bs[kq * 4 + 3][r] = bv.w;
        }
        __syncthreads();
#pragma unroll
        for (int kk = 0; kk < 16; kk++) {
            float a[8], b[8];
            *(float4*)(a)     = *(const float4*)&As[kk][ty * 4];
            *(float4*)(a + 4) = *(const float4*)&As[kk][64 + ty * 4];
            *(float4*)(b)     = *(const float4*)&Bs[kk][tx * 4];
            *(float4*)(b + 4) = *(const float4*)&Bs[kk][64 + tx * 4];
#pragma unroll
            for (int mi = 0; mi < 8; mi++)
#pragma unroll
                for (int ni = 0; ni < 8; ni++)
                    acc[mi][ni] += a[mi] * b[ni];
        }
        __syncthreads();
    }

    // Epilogue
#pragma unroll
    for (int mi = 0; mi < 8; mi++) {
        int rm = m0 + ((mi < 4) ? (ty * 4 + mi) : (64 + ty * 4 + mi - 4));
#pragma unroll
        for (int nh = 0; nh < 2; nh++) {
            int cn = n0 + nh * 64 + tx * 4;
            float4 bv = *(const float4*)(bias + cn);
            float4 o;
            o.x = acc[mi][nh * 4 + 0] + bv.x;
            o.y = acc[mi][nh * 4 + 1] + bv.y;
            o.z = acc[mi][nh * 4 + 2] + bv.z;
            o.w = acc[mi][nh * 4 + 3] + bv.w;
            if (MODE == 1) {
                *(float4*)(Cext + (size_t)rm * N + cn) = o;
            } else {
                int i3  = cn >> 10;
                int rem = cn & 1023;
                int h   = rem >> 6;
                int d   = rem & 63;
                int b_  = rm >> 11;
                int s   = rm & 2047;
                float* base = (i3 == 0) ? g_q : (i3 == 1) ? g_k : g_v;
                *(float4*)(base + ((size_t)((b_ * H_ + h) * S_) + s) * DH_ + d) = o;
            }
        }
    }
}

// ---------------------------------------------------------------------------
// RoPE in-place on g_q, g_k. One thread per (b,h,s,d2<32), handles d2 & d2+32.
// ---------------------------------------------------------------------------
__global__ __launch_bounds__(256) void rope_kernel(const int* __restrict__ p) {
    int idx = blockIdx.x * 256 + threadIdx.x;   // 4*16*2048*32 = 4194304 total
    int d2 = idx & 31;
    int s  = (idx >> 5) & 2047;
    int h  = (idx >> 16) & 15;
    int b  = idx >> 20;

    float f  = g_freqs[d2];
    float th = (float)p[b * S_ + s] * f;
    float sn, cs;
    sincosf(th, &sn, &cs);

    size_t base = ((size_t)((b * H_ + h) * S_) + s) * DH_;
    float q1 = g_q[base + d2], q2 = g_q[base + d2 + 32];
    g_q[base + d2]      = q1 * cs + q2 * sn;
    g_q[base + d2 + 32] = q2 * cs - q1 * sn;
    float k1 = g_k[base + d2], k2 = g_k[base + d2 + 32];
    g_k[base + d2]      = k1 * cs + k2 * sn;
    g_k[base + d2 + 32] = k2 * cs - k1 * sn;
}

// ---------------------------------------------------------------------------
// Flash attention v2: grid (S/64, H, B), block (16,16).
// Outer-product structure (GEMM-style):
//   Qt [d][q]  transposed, XOR-swizzled, scale folded in    (broadcast reads)
//   Kt [d][k]  transposed, XOR-swizzled -> float4 reads, conflict-free
//   After QK, Kt buffer reused for P stored NATURAL [q][k] (broadcast reads)
//   Vs [j][dc] natural (conflict-free float4 reads)
// Mainloops: QK = 2 LDS.128 + 16 FMA per d;  PV = 8 LDS.128 + 64 FMA per 4 j.
// Static smem = exactly 48KB.
// ---------------------------------------------------------------------------
__device__ __forceinline__ int SWZ(int d, int c) {
    return d * 64 + (c ^ ((d & 7) << 2));
}

__global__ __launch_bounds__(256) void flash_kernel() {
    const int tx = threadIdx.x, ty = threadIdx.y;
    const int tid = ty * 16 + tx;
    const int qb = blockIdx.x * 64;
    const int h  = blockIdx.y;
    const int b  = blockIdx.z;
    const size_t bh = (size_t)(b * H_ + h) * S_ * DH_;
    const float* Qg = g_q + bh;
    const float* Kg = g_k + bh;
    const float* Vg = g_v + bh;

    __shared__ float Qt[64 * 64];   // Q transposed [d][q], pre-scaled
    __shared__ float KPs[64 * 64];  // K transposed [d][k], then P natural [q][k]
    __shared__ float Vs[64 * 64];   // V natural [j][dc]

    // Transpose-load Q tile (scale folded in; 0.125 is exact)
    {
        int r = tid >> 2;       // 0..63 : q row
        int c = tid & 3;
#pragma unroll
        for (int i = 0; i < 4; i++) {
            int c4 = c + 4 * i; // float4 index along d
            float4 v = *(const float4*)(Qg + (size_t)(qb + r) * DH_ + c4 * 4);
            Qt[SWZ(4 * c4 + 0, r)] = v.x * SCALE_;
            Qt[SWZ(4 * c4 + 1, r)] = v.y * SCALE_;
            Qt[SWZ(4 * c4 + 2, r)] = v.z * SCALE_;
            Qt[SWZ(4 * c4 + 3, r)] = v.w * SCALE_;
        }
    }

    float m[4], l[4], acc[4][4];
#pragma unroll
    for (int qi = 0; qi < 4; qi++) {
        m[qi] = -CUDART_INF_F;
        l[qi] = 0.0f;
#pragma unroll
        for (int dc = 0; dc < 4; dc++) acc[qi][dc] = 0.0f;
    }

    for (int kt = 0; kt < S_; kt += 64) {
        __syncthreads();   // prev PV reads done (and Q store visible on iter 0)

        // Transpose-load K, natural-load V
        {
            int r = tid >> 2;
            int c = tid & 3;
#pragma unroll
            for (int i = 0; i < 4; i++) {
                int c4 = c + 4 * i;
                float4 kv = *(const float4*)(Kg + (size_t)(kt + r) * DH_ + c4 * 4);
                KPs[SWZ(4 * c4 + 0, r)] = kv.x;
                KPs[SWZ(4 * c4 + 1, r)] = kv.y;
                KPs[SWZ(4 * c4 + 2, r)] = kv.z;
                KPs[SWZ(4 * c4 + 3, r)] = kv.w;
            }
            int r2 = tid >> 4;      // 0..15
            int c2 = tid & 15;
#pragma unroll
            for (int i = 0; i < 4; i++) {
                int rr = r2 + 16 * i;
                *(float4*)&Vs[rr * 64 + c2 * 4] =
                    *(const float4*)(Vg + (size_t)(kt + rr) * DH_ + c2 * 4);
            }
        }
        __syncthreads();

        // S = Q K^T via outer products over d
        float sf[4][4];
#pragma unroll
        for (int qi = 0; qi < 4; qi++)
#pragma unroll
            for (int kj = 0; kj < 4; kj++) sf[qi][kj] = 0.0f;

#pragma unroll 16
        for (int d = 0; d < 64; d++) {
            float4 a  = *(const float4*)&Qt[SWZ(d, ty * 4)];
            float4 bk = *(const float4*)&KPs[SWZ(d, tx * 4)];
            float av[4] = {a.x, a.y, a.z, a.w};
            float bv[4] = {bk.x, bk.y, bk.z, bk.w};
#pragma unroll
            for (int qi = 0; qi < 4; qi++)
#pragma unroll
                for (int kj = 0; kj < 4; kj++)
                    sf[qi][kj] += av[qi] * bv[kj];
        }

        // Online softmax (row reductions over the 16-lane tx group)
#pragma unroll
        for (int qi = 0; qi < 4; qi++) {
            float mx = fmaxf(fmaxf(sf[qi][0], sf[qi][1]),
                             fmaxf(sf[qi][2], sf[qi][3]));
#pragma unroll
            for (int off = 8; off >= 1; off >>= 1)
                mx = fmaxf(mx, __shfl_xor_sync(0xffffffffu, mx, off));
            float mnew = fmaxf(m[qi], mx);
            float corr = __expf(m[qi] - mnew);
            float sum = 0.0f;
#pragma unroll
            for (int kj = 0; kj < 4; kj++) {
                float pv = __expf(sf[qi][kj] - mnew);
                sf[qi][kj] = pv;
                sum += pv;
            }
#pragma unroll
            for (int off = 8; off >= 1; off >>= 1)
                sum += __shfl_xor_sync(0xffffffffu, sum, off);
            l[qi] = l[qi] * corr + sum;
            m[qi] = mnew;
#pragma unroll
            for (int dc = 0; dc < 4; dc++) acc[qi][dc] *= corr;
        }

        __syncthreads();   // all QK reads of KPs complete
        // Store P natural [q][k] (float4, swizzled row base) into KPs
#pragma unroll
        for (int qi = 0; qi < 4; qi++) {
            int q = ty * 4 + qi;
            float4 pv = make_float4(sf[qi][0], sf[qi][1], sf[qi][2], sf[qi][3]);
            *(float4*)&KPs[q * 64 + ((tx * 4) ^ ((q & 7) << 2))] = pv;
        }
        __syncthreads();

        // O += P @ V  (P broadcast float4 along j, V conflict-free float4)
#pragma unroll 4
        for (int j0 = 0; j0 < 16; j0++) {
            float pr[4][4], vr[4][4];
#pragma unroll
            for (int qi = 0; qi < 4; qi++) {
                int q = ty * 4 + qi;
                float4 p = *(const float4*)&KPs[q * 64 + ((4 * j0) ^ ((q & 7) << 2))];
                pr[qi][0] = p.x; pr[qi][1] = p.y; pr[qi][2] = p.z; pr[qi][3] = p.w;
            }
#pragma unroll
            for (int jj = 0; jj < 4; jj++) {
                float4 v = *(const float4*)&Vs[(4 * j0 + jj) * 64 + tx * 4];
                vr[jj][0] = v.x; vr[jj][1] = v.y; vr[jj][2] = v.z; vr[jj][3] = v.w;
            }
#pragma unroll
            for (int qi = 0; qi < 4; qi++)
#pragma unroll
                for (int jj = 0; jj < 4; jj++)
#pragma unroll
                    for (int dc = 0; dc < 4; dc++)
                        acc[qi][dc] += pr[qi][jj] * vr[jj][dc];
        }
    }

    // Normalize and store into g_attn [B, S, D] (column block h*64)
#pragma unroll
    for (int qi = 0; qi < 4; qi++) {
        float inv = 1.0f / l[qi];
        int s = qb + ty * 4 + qi;
        float4 o;
        o.x = acc[qi][0] * inv;
        o.y = acc[qi][1] * inv;
        o.z = acc[qi][2] * inv;
        o.w = acc[qi][3] * inv;
        *(float4*)(g_attn + ((size_t)(b * S_ + s)) * D_ + h * 64 + tx * 4) = o;
    }
}

// ---------------------------------------------------------------------------
// Launch
// ---------------------------------------------------------------------------
extern "C" void kernel_launch(void* const* d_in, const int* in_sizes, int n_in,
                              void* d_out, int out_size) {
    const float* x      = (const float*)d_in[0];
    const int*   p      = (const int*)d_in[1];
    const float* Wqkv_w = (const float*)d_in[2];
    const float* Wqkv_b = (const float*)d_in[3];
    const float* Wo_w   = (const float*)d_in[4];
    const float* Wo_b   = (const float*)d_in[5];
    float* out = (float*)d_out;

    dim3 blk(16, 16);

    // 1. QKV projection + scatter into g_q/g_k/g_v
    gemm_kernel<0><<<dim3(3 * D_ / 128, (B_ * S_) / 128), blk>>>(
        x, Wqkv_w, Wqkv_b, nullptr, 3 * D_, D_);

    // 2. RoPE
    prep_freqs_kernel<<<1, 32>>>();
    rope_kernel<<<(B_ * H_ * S_ * 32) / 256, 256>>>(p);

    // 3. Flash attention -> g_attn
    flash_kernel<<<dim3(S_ / 64, H_, B_), blk>>>();

    // 4. Output projection
    gemm_kernel<1><<<dim3(D_ / 128, (B_ * S_) / 128), blk>>>(
        nullptr, Wo_w, Wo_b, out, D_, D_);
}

// round 5
// speedup vs baseline: 1.2919x; 1.0254x over previous
#include <cuda_runtime.h>
#include <math.h>
#include <math_constants.h>

#define B_  4
#define S_  2048
#define D_  1024
#define H_  16
#define DH_ 64
#define SCALE_ 0.125f

// Scratch (allocation-free rule: __device__ globals)
__device__ float g_q[(size_t)B_*H_*S_*DH_];
__device__ float g_k[(size_t)B_*H_*S_*DH_];
__device__ float g_v[(size_t)B_*H_*S_*DH_];
__device__ float g_attn[(size_t)B_*S_*D_];
__device__ float g_freqs[32];

// ---------------------------------------------------------------------------
// Freq prep: f[i] = 10000^(-i/32), computed in double -> correctly rounded f32
// ---------------------------------------------------------------------------
__global__ void prep_freqs_kernel() {
    int i = threadIdx.x;
    if (i < 32) {
        g_freqs[i] = (float)exp(-(double)i * (9.210340371976184 / 32.0));
    }
}

// ---------------------------------------------------------------------------
// GEMM: C[M,N] = A[M,K] @ W[N,K]^T + bias[N]
// MODE 0: A = x, scatter-store into g_q/g_k/g_v  (n -> (i3, h, d), m -> (b, s))
// MODE 1: A = g_attn, plain store to Cext (d_out)
// BM=BN=128, BK=16, 256 threads, 8x8 per thread (split 4+4 fragments)
// ---------------------------------------------------------------------------
template<int MODE>
__global__ __launch_bounds__(256) void gemm_kernel(
    const float* __restrict__ Aext, const float* __restrict__ W,
    const float* __restrict__ bias, float* __restrict__ Cext,
    int N, int K)
{
    const float* A = (MODE == 1) ? g_attn : Aext;
    const int m0 = blockIdx.y * 128;
    const int n0 = blockIdx.x * 128;
    const int tx = threadIdx.x, ty = threadIdx.y;
    const int tid = ty * 16 + tx;

    __shared__ float As[16][132];
    __shared__ float Bs[16][132];

    float acc[8][8];
#pragma unroll
    for (int i = 0; i < 8; i++)
#pragma unroll
        for (int j = 0; j < 8; j++) acc[i][j] = 0.0f;

    for (int k0 = 0; k0 < K; k0 += 16) {
#pragma unroll
        for (int i = 0; i < 2; i++) {
            int f  = tid + i * 256;
            int r  = f >> 2;
            int kq = f & 3;
            float4 av = *(const float4*)(A + (size_t)(m0 + r) * K + k0 + kq * 4);
            As[kq * 4 + 0][r] = av.x;
            As[kq * 4 + 1][r] = av.y;
            As[kq * 4 + 2][r] = av.z;
            As[kq * 4 + 3][r] = av.w;
            float4 bv = *(const float4*)(W + (size_t)(n0 + r) * K + k0 + kq * 4);
            Bs[kq * 4 + 0][r] = bv.x;
            Bs[kq * 4 + 1][r] = bv.y;
            Bs[kq * 4 + 2][r] = bv.z;
            Bs[kq * 4 + 3][r] = bv.w;
        }
        __syncthreads();
#pragma unroll
        for (int kk = 0; kk < 16; kk++) {
            float a[8], b[8];
            *(float4*)(a)     = *(const float4*)&As[kk][ty * 4];
            *(float4*)(a + 4) = *(const float4*)&As[kk][64 + ty * 4];
            *(float4*)(b)     = *(const float4*)&Bs[kk][tx * 4];
            *(float4*)(b + 4) = *(const float4*)&Bs[kk][64 + tx * 4];
#pragma unroll
            for (int mi = 0; mi < 8; mi++)
#pragma unroll
                for (int ni = 0; ni < 8; ni++)
                    acc[mi][ni] += a[mi] * b[ni];
        }
        __syncthreads();
    }

    // Epilogue
#pragma unroll
    for (int mi = 0; mi < 8; mi++) {
        int rm = m0 + ((mi < 4) ? (ty * 4 + mi) : (64 + ty * 4 + mi - 4));
#pragma unroll
        for (int nh = 0; nh < 2; nh++) {
            int cn = n0 + nh * 64 + tx * 4;
            float4 bv = *(const float4*)(bias + cn);
            float4 o;
            o.x = acc[mi][nh * 4 + 0] + bv.x;
            o.y = acc[mi][nh * 4 + 1] + bv.y;
            o.z = acc[mi][nh * 4 + 2] + bv.z;
            o.w = acc[mi][nh * 4 + 3] + bv.w;
            if (MODE == 1) {
                *(float4*)(Cext + (size_t)rm * N + cn) = o;
            } else {
                int i3  = cn >> 10;
                int rem = cn & 1023;
                int h   = rem >> 6;
                int d   = rem & 63;
                int b_  = rm >> 11;
                int s   = rm & 2047;
                float* base = (i3 == 0) ? g_q : (i3 == 1) ? g_k : g_v;
                *(float4*)(base + ((size_t)((b_ * H_ + h) * S_) + s) * DH_ + d) = o;
            }
        }
    }
}

// ---------------------------------------------------------------------------
// RoPE in-place on g_q, g_k. One thread per (b,h,s,d2<32), handles d2 & d2+32.
// ---------------------------------------------------------------------------
__global__ __launch_bounds__(256) void rope_kernel(const int* __restrict__ p) {
    int idx = blockIdx.x * 256 + threadIdx.x;   // 4*16*2048*32 = 4194304 total
    int d2 = idx & 31;
    int s  = (idx >> 5) & 2047;
    int h  = (idx >> 16) & 15;
    int b  = idx >> 20;

    float f  = g_freqs[d2];
    float th = (float)p[b * S_ + s] * f;
    float sn, cs;
    sincosf(th, &sn, &cs);

    size_t base = ((size_t)((b * H_ + h) * S_) + s) * DH_;
    float q1 = g_q[base + d2], q2 = g_q[base + d2 + 32];
    g_q[base + d2]      = q1 * cs + q2 * sn;
    g_q[base + d2 + 32] = q2 * cs - q1 * sn;
    float k1 = g_k[base + d2], k2 = g_k[base + d2 + 32];
    g_k[base + d2]      = k1 * cs + k2 * sn;
    g_k[base + d2 + 32] = k2 * cs - k1 * sn;
}

// ---------------------------------------------------------------------------
// Flash attention v3: Br=128, Bc=128, block (16,16), dynamic smem 128KB.
// Layout (floats, dynamic smem):
//   Qt  [64][128]   @ 0      transposed [d][q], XOR-swizzled, pre-scaled
//   Pb  [128][128]  @ 8192   dual-use: Kt [d][k] (first 64 rows) during QK,
//                            then P natural [q][k] (row-swizzled) for PV
//   Vs  [128][64]   @ 24576  natural [j][dh]
// Fragments: sf[8][8] (q = ty*4 split 4+4, k = tx*4 split 4+4),
//            acc[8][4] (dh = tx*4).
// QK: per d = 4 LDS.128 + 64 FMA.  PV: per 4j = 12 LDS.128 + 128 FMA.
// ---------------------------------------------------------------------------
__device__ __forceinline__ int FSWZ(int d, int c) {   // 128-wide rows
    return d * 128 + (c ^ ((d & 31) << 2));
}

__global__ __launch_bounds__(256) void flash_kernel() {
    const int tx = threadIdx.x, ty = threadIdx.y;
    const int tid = ty * 16 + tx;
    const int qb = blockIdx.x * 128;
    const int h  = blockIdx.y;
    const int b  = blockIdx.z;
    const size_t bh = (size_t)(b * H_ + h) * S_ * DH_;
    const float* Qg = g_q + bh;
    const float* Kg = g_k + bh;
    const float* Vg = g_v + bh;

    extern __shared__ float sm[];
    float* Qt = sm;                 // 8192 floats
    float* Pb = sm + 8192;          // 16384 floats (Kt aliases rows 0..63)
    float* Vs = sm + 8192 + 16384;  // 8192 floats

    // Transpose-load Q tile (128 rows x 64 d), scale folded in
    {
        int r  = tid >> 1;          // 0..127 q row
        int ch = tid & 1;
#pragma unroll
        for (int i = 0; i < 8; i++) {
            int c4 = ch * 8 + i;    // float4 index along d
            float4 v = *(const float4*)(Qg + (size_t)(qb + r) * DH_ + c4 * 4);
            Qt[FSWZ(4 * c4 + 0, r)] = v.x * SCALE_;
            Qt[FSWZ(4 * c4 + 1, r)] = v.y * SCALE_;
            Qt[FSWZ(4 * c4 + 2, r)] = v.z * SCALE_;
            Qt[FSWZ(4 * c4 + 3, r)] = v.w * SCALE_;
        }
    }

    float m[8], l[8], acc[8][4];
#pragma unroll
    for (int qi = 0; qi < 8; qi++) {
        m[qi] = -CUDART_INF_F;
        l[qi] = 0.0f;
#pragma unroll
        for (int dc = 0; dc < 4; dc++) acc[qi][dc] = 0.0f;
    }

    for (int kt = 0; kt < S_; kt += 128) {
        __syncthreads();   // prev PV reads done (and Q stores visible, iter 0)

        // Transpose-load K (128 rows -> Kt[d][k] in Pb), natural-load V
        {
            int r  = tid >> 1;
            int ch = tid & 1;
#pragma unroll
            for (int i = 0; i < 8; i++) {
                int c4 = ch * 8 + i;
                float4 kv = *(const float4*)(Kg + (size_t)(kt + r) * DH_ + c4 * 4);
                Pb[FSWZ(4 * c4 + 0, r)] = kv.x;
                Pb[FSWZ(4 * c4 + 1, r)] = kv.y;
                Pb[FSWZ(4 * c4 + 2, r)] = kv.z;
                Pb[FSWZ(4 * c4 + 3, r)] = kv.w;
            }
            int r2 = tid >> 4;      // 0..15
            int c2 = tid & 15;
#pragma unroll
            for (int i = 0; i < 8; i++) {
                int rr = r2 + 16 * i;
                *(float4*)&Vs[rr * 64 + c2 * 4] =
                    *(const float4*)(Vg + (size_t)(kt + rr) * DH_ + c2 * 4);
            }
        }
        __syncthreads();

        // S = Q K^T via outer products over d  (Kt lives in Pb rows 0..63)
        float sf[8][8];
#pragma unroll
        for (int qi = 0; qi < 8; qi++)
#pragma unroll
            for (int kj = 0; kj < 8; kj++) sf[qi][kj] = 0.0f;

#pragma unroll 8
        for (int d = 0; d < 64; d++) {
            float a[8], bb[8];
            *(float4*)(a)      = *(const float4*)&Qt[FSWZ(d, ty * 4)];
            *(float4*)(a + 4)  = *(const float4*)&Qt[FSWZ(d, 64 + ty * 4)];
            *(float4*)(bb)     = *(const float4*)&Pb[FSWZ(d, tx * 4)];
            *(float4*)(bb + 4) = *(const float4*)&Pb[FSWZ(d, 64 + tx * 4)];
#pragma unroll
            for (int qi = 0; qi < 8; qi++)
#pragma unroll
                for (int kj = 0; kj < 8; kj++)
                    sf[qi][kj] += a[qi] * bb[kj];
        }

        // Online softmax (row reductions over the 16-lane tx group)
#pragma unroll
        for (int qi = 0; qi < 8; qi++) {
            float mx = sf[qi][0];
#pragma unroll
            for (int kj = 1; kj < 8; kj++) mx = fmaxf(mx, sf[qi][kj]);
#pragma unroll
            for (int off = 8; off >= 1; off >>= 1)
                mx = fmaxf(mx, __shfl_xor_sync(0xffffffffu, mx, off));
            float mnew = fmaxf(m[qi], mx);
            float corr = __expf(m[qi] - mnew);
            float sum = 0.0f;
#pragma unroll
            for (int kj = 0; kj < 8; kj++) {
                float pv = __expf(sf[qi][kj] - mnew);
                sf[qi][kj] = pv;
                sum += pv;
            }
#pragma unroll
            for (int off = 8; off >= 1; off >>= 1)
                sum += __shfl_xor_sync(0xffffffffu, sum, off);
            l[qi] = l[qi] * corr + sum;
            m[qi] = mnew;
#pragma unroll
            for (int dc = 0; dc < 4; dc++) acc[qi][dc] *= corr;
        }

        __syncthreads();   // all QK reads of Kt (in Pb) complete

        // Store P natural [q][k] (two swizzled float4 per q row)
#pragma unroll
        for (int qi = 0; qi < 8; qi++) {
            int q = (qi < 4) ? (ty * 4 + qi) : (64 + ty * 4 + qi - 4);
            int s = (q & 31) << 2;
            *(float4*)&Pb[q * 128 + ((tx * 4) ^ s)] =
                make_float4(sf[qi][0], sf[qi][1], sf[qi][2], sf[qi][3]);
            *(float4*)&Pb[q * 128 + ((64 + tx * 4) ^ s)] =
                make_float4(sf[qi][4], sf[qi][5], sf[qi][6], sf[qi][7]);
        }
        __syncthreads();

        // O += P @ V   (P broadcast float4 along j, V full-bw float4)
#pragma unroll 4
        for (int j0 = 0; j0 < 128; j0 += 4) {
            float pr[8][4], vr[4][4];
#pragma unroll
            for (int qi = 0; qi < 8; qi++) {
                int q = (qi < 4) ? (ty * 4 + qi) : (64 + ty * 4 + qi - 4);
                float4 p = *(const float4*)&Pb[q * 128 + (j0 ^ ((q & 31) << 2))];
                pr[qi][0] = p.x; pr[qi][1] = p.y; pr[qi][2] = p.z; pr[qi][3] = p.w;
            }
#pragma unroll
            for (int jj = 0; jj < 4; jj++) {
                float4 v = *(const float4*)&Vs[(j0 + jj) * 64 + tx * 4];
                vr[jj][0] = v.x; vr[jj][1] = v.y; vr[jj][2] = v.z; vr[jj][3] = v.w;
            }
#pragma unroll
            for (int qi = 0; qi < 8; qi++)
#pragma unroll
                for (int jj = 0; jj < 4; jj++)
#pragma unroll
                    for (int dc = 0; dc < 4; dc++)
                        acc[qi][dc] += pr[qi][jj] * vr[jj][dc];
        }
    }

    // Normalize and store into g_attn [B, S, D] (column block h*64)
#pragma unroll
    for (int qi = 0; qi < 8; qi++) {
        float inv = 1.0f / l[qi];
        int s = qb + ((qi < 4) ? (ty * 4 + qi) : (64 + ty * 4 + qi - 4));
        float4 o;
        o.x = acc[qi][0] * inv;
        o.y = acc[qi][1] * inv;
        o.z = acc[qi][2] * inv;
        o.w = acc[qi][3] * inv;
        *(float4*)(g_attn + ((size_t)(b * S_ + s)) * D_ + h * 64 + tx * 4) = o;
    }
}

// ---------------------------------------------------------------------------
// Launch
// ---------------------------------------------------------------------------
extern "C" void kernel_launch(void* const* d_in, const int* in_sizes, int n_in,
                              void* d_out, int out_size) {
    const float* x      = (const float*)d_in[0];
    const int*   p      = (const int*)d_in[1];
    const float* Wqkv_w = (const float*)d_in[2];
    const float* Wqkv_b = (const float*)d_in[3];
    const float* Wo_w   = (const float*)d_in[4];
    const float* Wo_b   = (const float*)d_in[5];
    float* out = (float*)d_out;

    dim3 blk(16, 16);
    const int FLASH_SMEM = 128 * 1024;
    cudaFuncSetAttribute(flash_kernel,
                         cudaFuncAttributeMaxDynamicSharedMemorySize, FLASH_SMEM);

    // 1. QKV projection + scatter into g_q/g_k/g_v
    gemm_kernel<0><<<dim3(3 * D_ / 128, (B_ * S_) / 128), blk>>>(
        x, Wqkv_w, Wqkv_b, nullptr, 3 * D_, D_);

    // 2. RoPE
    prep_freqs_kernel<<<1, 32>>>();
    rope_kernel<<<(B_ * H_ * S_ * 32) / 256, 256>>>(p);

    // 3. Flash attention -> g_attn
    flash_kernel<<<dim3(S_ / 128, H_, B_), blk, FLASH_SMEM>>>();

    // 4. Output projection
    gemm_kernel<1><<<dim3(D_ / 128, (B_ * S_) / 128), blk>>>(
        nullptr, Wo_w, Wo_b, out, D_, D_);
}

// round 9
// speedup vs baseline: 1.7766x; 1.3752x over previous
#include <cuda_runtime.h>
#include <cuda_bf16.h>
#include <cstdint>
#include <math.h>
#include <math_constants.h>

#define B_  4
#define S_  2048
#define D_  1024
#define H_  16
#define DH_ 64
#define SCALE_ 0.125f

// ---------------------------------------------------------------------------
// Scratch (allocation-free rule: __device__ globals)
// ---------------------------------------------------------------------------
__device__ float g_q[(size_t)B_*H_*S_*DH_];
__device__ float g_k[(size_t)B_*H_*S_*DH_];
__device__ float g_v[(size_t)B_*H_*S_*DH_];
__device__ float g_attn[(size_t)B_*S_*D_];
__device__ float g_freqs[32];

// bf16 hi/lo split operands for tensor-core GEMMs
__device__ __nv_bfloat16 g_xh[(size_t)B_*S_*D_];
__device__ __nv_bfloat16 g_xl[(size_t)B_*S_*D_];
__device__ __nv_bfloat16 g_wqh[(size_t)3*D_*D_];
__device__ __nv_bfloat16 g_wql[(size_t)3*D_*D_];
__device__ __nv_bfloat16 g_aoh[(size_t)B_*S_*D_];
__device__ __nv_bfloat16 g_aol[(size_t)B_*S_*D_];
__device__ __nv_bfloat16 g_woh[(size_t)D_*D_];
__device__ __nv_bfloat16 g_wol[(size_t)D_*D_];

// ---------------------------------------------------------------------------
// PTX helpers (sm_80-class features only: compile at compute_103 base target)
// ---------------------------------------------------------------------------
__device__ __forceinline__ uint32_t smem_u32(const void* p) {
    uint32_t a;
    asm("{ .reg .u64 t; cvta.to.shared.u64 t, %1; cvt.u32.u64 %0, t; }"
        : "=r"(a) : "l"(p));
    return a;
}

__device__ __forceinline__ void cp_async16(uint32_t saddr, const void* gaddr) {
    asm volatile("cp.async.cg.shared.global [%0], [%1], 16;"
                 :: "r"(saddr), "l"(gaddr));
}
__device__ __forceinline__ void cp_commit() {
    asm volatile("cp.async.commit_group;");
}
template<int N>
__device__ __forceinline__ void cp_wait() {
    asm volatile("cp.async.wait_group %0;" :: "n"(N));
}

__device__ __forceinline__ void ldsm_x4(uint32_t* r, uint32_t addr) {
    asm volatile("ldmatrix.sync.aligned.m8n8.x4.shared.b16 {%0,%1,%2,%3}, [%4];"
                 : "=r"(r[0]), "=r"(r[1]), "=r"(r[2]), "=r"(r[3]) : "r"(addr));
}
__device__ __forceinline__ void ldsm_x2(uint32_t* r, uint32_t addr) {
    asm volatile("ldmatrix.sync.aligned.m8n8.x2.shared.b16 {%0,%1}, [%2];"
                 : "=r"(r[0]), "=r"(r[1]) : "r"(addr));
}

__device__ __forceinline__ void mma16816(float* d, const uint32_t* a,
                                         const uint32_t* b) {
    asm volatile(
        "mma.sync.aligned.m16n8k16.row.col.f32.bf16.bf16.f32 "
        "{%0,%1,%2,%3}, {%4,%5,%6,%7}, {%8,%9}, {%0,%1,%2,%3};"
        : "+f"(d[0]), "+f"(d[1]), "+f"(d[2]), "+f"(d[3])
        : "r"(a[0]), "r"(a[1]), "r"(a[2]), "r"(a[3]), "r"(b[0]), "r"(b[1]));
}

// ---------------------------------------------------------------------------
// Freq prep
// ---------------------------------------------------------------------------
__global__ void prep_freqs_kernel() {
    int i = threadIdx.x;
    if (i < 32) {
        g_freqs[i] = (float)exp(-(double)i * (9.210340371976184 / 32.0));
    }
}

// ---------------------------------------------------------------------------
// fp32 -> bf16 hi/lo split (4 floats per thread)
// ---------------------------------------------------------------------------
__global__ __launch_bounds__(256) void convert_hilo_kernel(
    const float* __restrict__ src, __nv_bfloat16* __restrict__ hi,
    __nv_bfloat16* __restrict__ lo)
{
    int i = (blockIdx.x * 256 + threadIdx.x) * 4;
    float4 v = *(const float4*)(src + i);
    __nv_bfloat16 h0 = __float2bfloat16(v.x);
    __nv_bfloat16 h1 = __float2bfloat16(v.y);
    __nv_bfloat16 h2 = __float2bfloat16(v.z);
    __nv_bfloat16 h3 = __float2bfloat16(v.w);
    __nv_bfloat16 l0 = __float2bfloat16(v.x - __bfloat162float(h0));
    __nv_bfloat16 l1 = __float2bfloat16(v.y - __bfloat162float(h1));
    __nv_bfloat16 l2 = __float2bfloat16(v.z - __bfloat162float(h2));
    __nv_bfloat16 l3 = __float2bfloat16(v.w - __bfloat162float(h3));
    *(__nv_bfloat162*)(hi + i)     = __halves2bfloat162(h0, h1);
    *(__nv_bfloat162*)(hi + i + 2) = __halves2bfloat162(h2, h3);
    *(__nv_bfloat162*)(lo + i)     = __halves2bfloat162(l0, l1);
    *(__nv_bfloat162*)(lo + i + 2) = __halves2bfloat162(l2, l3);
}

// ---------------------------------------------------------------------------
// Tensor-core GEMM via mma.sync bf16x3: C = (Ah+Al)(Bh+Bl)^T + bias
//   ~= Ah*Bh + Al*Bh + Ah*Bl  (fp32 register accumulators)
// A[M,1024], B[N,1024] both K-major bf16 (hi/lo pairs).
// Tile: BM=128, BN=128, BK=32. 256 threads = 8 warps (2m x 4n), warp 64x32.
// 2-stage cp.async pipeline. Smem/stage: Ah,Al,Bh,Bl each 128x32 bf16 (8KB).
// Swizzle: 16B chunk c of row r stored at c ^ ((r>>1)&3).
// MODE 0: scatter epilogue into g_q/g_k/g_v.  MODE 1: bias+store to Cext.
// ---------------------------------------------------------------------------
#define STG_BYTES 32768   // 4 tiles * 8KB
#define TCG_SMEM  65536   // 2 stages

__device__ __forceinline__ void issue_tile(const __nv_bfloat16* __restrict__ g,
                                           int row0, int k0, uint32_t sbase,
                                           int tid) {
#pragma unroll
    for (int j = 0; j < 2; j++) {
        int idx = tid + j * 256;
        int r = idx >> 2, c = idx & 3;
        const void* gp = g + (size_t)(row0 + r) * 1024 + k0 + c * 8;
        uint32_t sp = sbase + r * 64 + ((c ^ ((r >> 1) & 3)) << 4);
        cp_async16(sp, gp);
    }
}

template<int MODE>
__global__ __launch_bounds__(256) void tc_gemm_kernel(
    const __nv_bfloat16* __restrict__ Ah, const __nv_bfloat16* __restrict__ Al,
    const __nv_bfloat16* __restrict__ Bh, const __nv_bfloat16* __restrict__ Bl,
    const float* __restrict__ bias, float* __restrict__ Cext, int N)
{
    extern __shared__ char smc[];
    const uint32_t sb = smem_u32(smc);
    const int tid  = threadIdx.x;
    const int lane = tid & 31;
    const int wid  = tid >> 5;
    const int wm   = wid >> 2;        // 0..1 -> m offset wm*64
    const int wn   = wid & 3;         // 0..3 -> n offset wn*32
    const int m0 = blockIdx.y * 128;
    const int n0 = blockIdx.x * 128;

    float acc[4][4][4];
#pragma unroll
    for (int mi = 0; mi < 4; mi++)
#pragma unroll
        for (int nj = 0; nj < 4; nj++)
#pragma unroll
            for (int e = 0; e < 4; e++) acc[mi][nj][e] = 0.0f;

    // Preload stage 0
    issue_tile(Ah, m0, 0, sb,         tid);
    issue_tile(Al, m0, 0, sb + 8192,  tid);
    issue_tile(Bh, n0, 0, sb + 16384, tid);
    issue_tile(Bl, n0, 0, sb + 24576, tid);
    cp_commit();

    int buf = 0;
    for (int it = 0; it < 32; it++) {
        if (it + 1 < 32) {
            uint32_t nb = sb + (buf ^ 1) * STG_BYTES;
            int k0 = (it + 1) * 32;
            issue_tile(Ah, m0, k0, nb,         tid);
            issue_tile(Al, m0, k0, nb + 8192,  tid);
            issue_tile(Bh, n0, k0, nb + 16384, tid);
            issue_tile(Bl, n0, k0, nb + 24576, tid);
            cp_commit();
            cp_wait<1>();
        } else {
            cp_wait<0>();
        }
        __syncthreads();

        const uint32_t sA = sb + buf * STG_BYTES;
#pragma unroll
        for (int ks = 0; ks < 2; ks++) {
            uint32_t ah[4][4], al[4][4], bh[4][2], bl[4][2];
#pragma unroll
            for (int mi = 0; mi < 4; mi++) {
                int row = wm * 64 + mi * 16 + (lane & 15);
                int ch  = ks * 2 + (lane >> 4);
                uint32_t ad = sA + row * 64 + ((ch ^ ((row >> 1) & 3)) << 4);
                ldsm_x4(ah[mi], ad);
                ldsm_x4(al[mi], ad + 8192);
            }
#pragma unroll
            for (int nj = 0; nj < 4; nj++) {
                int row = wn * 32 + nj * 8 + (lane & 7);
                int ch  = ks * 2 + ((lane >> 3) & 1);
                uint32_t bd = sA + 16384 + row * 64 + ((ch ^ ((row >> 1) & 3)) << 4);
                ldsm_x2(bh[nj], bd);
                ldsm_x2(bl[nj], bd + 8192);
            }
#pragma unroll
            for (int mi = 0; mi < 4; mi++)
#pragma unroll
                for (int nj = 0; nj < 4; nj++) {
                    mma16816(acc[mi][nj], ah[mi], bh[nj]);
                    mma16816(acc[mi][nj], al[mi], bh[nj]);
                    mma16816(acc[mi][nj], ah[mi], bl[nj]);
                }
        }
        __syncthreads();
        buf ^= 1;
    }

    // Epilogue
    const int gr = lane >> 2;
    const int gc = (lane & 3) * 2;
#pragma unroll
    for (int mi = 0; mi < 4; mi++) {
#pragma unroll
        for (int nj = 0; nj < 4; nj++) {
            int col = n0 + wn * 32 + nj * 8 + gc;
            float b0 = bias[col], b1 = bias[col + 1];
#pragma unroll
            for (int half = 0; half < 2; half++) {
                int row = m0 + wm * 64 + mi * 16 + gr + half * 8;
                float2 o;
                o.x = acc[mi][nj][half * 2 + 0] + b0;
                o.y = acc[mi][nj][half * 2 + 1] + b1;
                if (MODE == 1) {
                    *(float2*)(Cext + (size_t)row * N + col) = o;
                } else {
                    int i3  = col >> 10;
                    int rem = col & 1023;
                    int h   = rem >> 6;
                    int d   = rem & 63;
                    int b_  = row >> 11;
                    int s   = row & 2047;
                    float* base = (i3 == 0) ? g_q : (i3 == 1) ? g_k : g_v;
                    *(float2*)(base + ((size_t)((b_ * H_ + h) * S_) + s) * DH_ + d) = o;
                }
            }
        }
    }
}

// ---------------------------------------------------------------------------
// RoPE in-place on g_q, g_k.
// ---------------------------------------------------------------------------
__global__ __launch_bounds__(256) void rope_kernel(const int* __restrict__ p) {
    int idx = blockIdx.x * 256 + threadIdx.x;
    int d2 = idx & 31;
    int s  = (idx >> 5) & 2047;
    int h  = (idx >> 16) & 15;
    int b  = idx >> 20;

    float f  = g_freqs[d2];
    float th = (float)p[b * S_ + s] * f;
    float sn, cs;
    sincosf(th, &sn, &cs);

    size_t base = ((size_t)((b * H_ + h) * S_) + s) * DH_;
    float q1 = g_q[base + d2], q2 = g_q[base + d2 + 32];
    g_q[base + d2]      = q1 * cs + q2 * sn;
    g_q[base + d2 + 32] = q2 * cs - q1 * sn;
    float k1 = g_k[base + d2], k2 = g_k[base + d2 + 32];
    g_k[base + d2]      = k1 * cs + k2 * sn;
    g_k[base + d2 + 32] = k2 * cs - k1 * sn;
}

// ---------------------------------------------------------------------------
// Flash attention (unchanged, known-good): Br=128, Bc=128, 128KB smem
// ---------------------------------------------------------------------------
__device__ __forceinline__ int FSWZ(int d, int c) {
    return d * 128 + (c ^ ((d & 31) << 2));
}

__global__ __launch_bounds__(256) void flash_kernel() {
    const int tx = threadIdx.x, ty = threadIdx.y;
    const int tid = ty * 16 + tx;
    const int qb = blockIdx.x * 128;
    const int h  = blockIdx.y;
    const int b  = blockIdx.z;
    const size_t bh = (size_t)(b * H_ + h) * S_ * DH_;
    const float* Qg = g_q + bh;
    const float* Kg = g_k + bh;
    const float* Vg = g_v + bh;

    extern __shared__ float sm[];
    float* Qt = sm;
    float* Pb = sm + 8192;
    float* Vs = sm + 8192 + 16384;

    {
        int r  = tid >> 1;
        int ch = tid & 1;
#pragma unroll
        for (int i = 0; i < 8; i++) {
            int c4 = ch * 8 + i;
            float4 v = *(const float4*)(Qg + (size_t)(qb + r) * DH_ + c4 * 4);
            Qt[FSWZ(4 * c4 + 0, r)] = v.x * SCALE_;
            Qt[FSWZ(4 * c4 + 1, r)] = v.y * SCALE_;
            Qt[FSWZ(4 * c4 + 2, r)] = v.z * SCALE_;
            Qt[FSWZ(4 * c4 + 3, r)] = v.w * SCALE_;
        }
    }

    float m[8], l[8], acc[8][4];
#pragma unroll
    for (int qi = 0; qi < 8; qi++) {
        m[qi] = -CUDART_INF_F;
        l[qi] = 0.0f;
#pragma unroll
        for (int dc = 0; dc < 4; dc++) acc[qi][dc] = 0.0f;
    }

    for (int kt = 0; kt < S_; kt += 128) {
        __syncthreads();
        {
            int r  = tid >> 1;
            int ch = tid & 1;
#pragma unroll
            for (int i = 0; i < 8; i++) {
                int c4 = ch * 8 + i;
                float4 kv = *(const float4*)(Kg + (size_t)(kt + r) * DH_ + c4 * 4);
                Pb[FSWZ(4 * c4 + 0, r)] = kv.x;
                Pb[FSWZ(4 * c4 + 1, r)] = kv.y;
                Pb[FSWZ(4 * c4 + 2, r)] = kv.z;
                Pb[FSWZ(4 * c4 + 3, r)] = kv.w;
            }
            int r2 = tid >> 4;
            int c2 = tid & 15;
#pragma unroll
            for (int i = 0; i < 8; i++) {
                int rr = r2 + 16 * i;
                *(float4*)&Vs[rr * 64 + c2 * 4] =
                    *(const float4*)(Vg + (size_t)(kt + rr) * DH_ + c2 * 4);
            }
        }
        __syncthreads();

        float sf[8][8];
#pragma unroll
        for (int qi = 0; qi < 8; qi++)
#pragma unroll
            for (int kj = 0; kj < 8; kj++) sf[qi][kj] = 0.0f;

#pragma unroll 8
        for (int d = 0; d < 64; d++) {
            float a[8], bb[8];
            *(float4*)(a)      = *(const float4*)&Qt[FSWZ(d, ty * 4)];
            *(float4*)(a + 4)  = *(const float4*)&Qt[FSWZ(d, 64 + ty * 4)];
            *(float4*)(bb)     = *(const float4*)&Pb[FSWZ(d, tx * 4)];
            *(float4*)(bb + 4) = *(const float4*)&Pb[FSWZ(d, 64 + tx * 4)];
#pragma unroll
            for (int qi = 0; qi < 8; qi++)
#pragma unroll
                for (int kj = 0; kj < 8; kj++)
                    sf[qi][kj] += a[qi] * bb[kj];
        }

#pragma unroll
        for (int qi = 0; qi < 8; qi++) {
            float mx = sf[qi][0];
#pragma unroll
            for (int kj = 1; kj < 8; kj++) mx = fmaxf(mx, sf[qi][kj]);
#pragma unroll
            for (int off = 8; off >= 1; off >>= 1)
                mx = fmaxf(mx, __shfl_xor_sync(0xffffffffu, mx, off));
            float mnew = fmaxf(m[qi], mx);
            float corr = __expf(m[qi] - mnew);
            float sum = 0.0f;
#pragma unroll
            for (int kj = 0; kj < 8; kj++) {
                float pv = __expf(sf[qi][kj] - mnew);
                sf[qi][kj] = pv;
                sum += pv;
            }
#pragma unroll
            for (int off = 8; off >= 1; off >>= 1)
                sum += __shfl_xor_sync(0xffffffffu, sum, off);
            l[qi] = l[qi] * corr + sum;
            m[qi] = mnew;
#pragma unroll
            for (int dc = 0; dc < 4; dc++) acc[qi][dc] *= corr;
        }

        __syncthreads();
#pragma unroll
        for (int qi = 0; qi < 8; qi++) {
            int q = (qi < 4) ? (ty * 4 + qi) : (64 + ty * 4 + qi - 4);
            int s = (q & 31) << 2;
            *(float4*)&Pb[q * 128 + ((tx * 4) ^ s)] =
                make_float4(sf[qi][0], sf[qi][1], sf[qi][2], sf[qi][3]);
            *(float4*)&Pb[q * 128 + ((64 + tx * 4) ^ s)] =
                make_float4(sf[qi][4], sf[qi][5], sf[qi][6], sf[qi][7]);
        }
        __syncthreads();

#pragma unroll 4
        for (int j0 = 0; j0 < 128; j0 += 4) {
            float pr[8][4], vr[4][4];
#pragma unroll
            for (int qi = 0; qi < 8; qi++) {
                int q = (qi < 4) ? (ty * 4 + qi) : (64 + ty * 4 + qi - 4);
                float4 p = *(const float4*)&Pb[q * 128 + (j0 ^ ((q & 31) << 2))];
                pr[qi][0] = p.x; pr[qi][1] = p.y; pr[qi][2] = p.z; pr[qi][3] = p.w;
            }
#pragma unroll
            for (int jj = 0; jj < 4; jj++) {
                float4 v = *(const float4*)&Vs[(j0 + jj) * 64 + tx * 4];
                vr[jj][0] = v.x; vr[jj][1] = v.y; vr[jj][2] = v.z; vr[jj][3] = v.w;
            }
#pragma unroll
            for (int qi = 0; qi < 8; qi++)
#pragma unroll
                for (int jj = 0; jj < 4; jj++)
#pragma unroll
                    for (int dc = 0; dc < 4; dc++)
                        acc[qi][dc] += pr[qi][jj] * vr[jj][dc];
        }
    }

#pragma unroll
    for (int qi = 0; qi < 8; qi++) {
        float inv = 1.0f / l[qi];
        int s = qb + ((qi < 4) ? (ty * 4 + qi) : (64 + ty * 4 + qi - 4));
        float4 o;
        o.x = acc[qi][0] * inv;
        o.y = acc[qi][1] * inv;
        o.z = acc[qi][2] * inv;
        o.w = acc[qi][3] * inv;
        *(float4*)(g_attn + ((size_t)(b * S_ + s)) * D_ + h * 64 + tx * 4) = o;
    }
}

// ---------------------------------------------------------------------------
// Launch
// ---------------------------------------------------------------------------
extern "C" void kernel_launch(void* const* d_in, const int* in_sizes, int n_in,
                              void* d_out, int out_size) {
    const float* x      = (const float*)d_in[0];
    const int*   p      = (const int*)d_in[1];
    const float* Wqkv_w = (const float*)d_in[2];
    const float* Wqkv_b = (const float*)d_in[3];
    const float* Wo_w   = (const float*)d_in[4];
    const float* Wo_b   = (const float*)d_in[5];
    float* out = (float*)d_out;

    const int FLASH_SMEM = 128 * 1024;
    cudaFuncSetAttribute(flash_kernel,
                         cudaFuncAttributeMaxDynamicSharedMemorySize, FLASH_SMEM);
    cudaFuncSetAttribute(tc_gemm_kernel<0>,
                         cudaFuncAttributeMaxDynamicSharedMemorySize, TCG_SMEM);
    cudaFuncSetAttribute(tc_gemm_kernel<1>,
                         cudaFuncAttributeMaxDynamicSharedMemorySize, TCG_SMEM);

    // Resolve device-global scratch addresses (pure lookups; capture-safe)
    __nv_bfloat16 *xh, *xl, *wqh, *wql, *aoh, *aol, *woh, *wol;
    cudaGetSymbolAddress((void**)&xh,  g_xh);
    cudaGetSymbolAddress((void**)&xl,  g_xl);
    cudaGetSymbolAddress((void**)&wqh, g_wqh);
    cudaGetSymbolAddress((void**)&wql, g_wql);
    cudaGetSymbolAddress((void**)&aoh, g_aoh);
    cudaGetSymbolAddress((void**)&aol, g_aol);
    cudaGetSymbolAddress((void**)&woh, g_woh);
    cudaGetSymbolAddress((void**)&wol, g_wol);
    float* attn;
    cudaGetSymbolAddress((void**)&attn, g_attn);

    // 0. Conversions + freqs
    convert_hilo_kernel<<<(B_ * S_ * D_) / 1024, 256>>>(x, xh, xl);
    convert_hilo_kernel<<<(3 * D_ * D_) / 1024, 256>>>(Wqkv_w, wqh, wql);
    convert_hilo_kernel<<<(D_ * D_) / 1024, 256>>>(Wo_w, woh, wol);
    prep_freqs_kernel<<<1, 32>>>();

    // 1. QKV projection (mma.sync bf16x3) + scatter into g_q/g_k/g_v
    tc_gemm_kernel<0><<<dim3(3 * D_ / 128, (B_ * S_) / 128), 256, TCG_SMEM>>>(
        xh, xl, wqh, wql, Wqkv_b, nullptr, 3 * D_);

    // 2. RoPE
    rope_kernel<<<(B_ * H_ * S_ * 32) / 256, 256>>>(p);

    // 3. Flash attention -> g_attn
    flash_kernel<<<dim3(S_ / 128, H_, B_), dim3(16, 16), FLASH_SMEM>>>();

    // 4. Convert attn output, then output projection (mma.sync bf16x3)
    convert_hilo_kernel<<<(B_ * S_ * D_) / 1024, 256>>>(attn, aoh, aol);
    tc_gemm_kernel<1><<<dim3(D_ / 128, (B_ * S_) / 128), 256, TCG_SMEM>>>(
        aoh, aol, woh, wol, Wo_b, out, D_);
}

// round 11
// speedup vs baseline: 3.6289x; 2.0426x over previous
#include <cuda_runtime.h>
#include <cuda_bf16.h>
#include <cstdint>
#include <math.h>
#include <math_constants.h>

#define B_  4
#define S_  2048
#define D_  1024
#define H_  16
#define DH_ 64
#define SCALE_ 0.125f

// ---------------------------------------------------------------------------
// Scratch (allocation-free rule: __device__ globals)
// ---------------------------------------------------------------------------
__device__ float g_q[(size_t)B_*H_*S_*DH_];
__device__ float g_k[(size_t)B_*H_*S_*DH_];
__device__ float g_v[(size_t)B_*H_*S_*DH_];
__device__ float g_attn[(size_t)B_*S_*D_];
__device__ float g_freqs[32];

// bf16 hi/lo split operands
__device__ __nv_bfloat16 g_xh[(size_t)B_*S_*D_];
__device__ __nv_bfloat16 g_xl[(size_t)B_*S_*D_];
__device__ __nv_bfloat16 g_wqh[(size_t)3*D_*D_];
__device__ __nv_bfloat16 g_wql[(size_t)3*D_*D_];
__device__ __nv_bfloat16 g_aoh[(size_t)B_*S_*D_];
__device__ __nv_bfloat16 g_aol[(size_t)B_*S_*D_];
__device__ __nv_bfloat16 g_woh[(size_t)D_*D_];
__device__ __nv_bfloat16 g_wol[(size_t)D_*D_];
// RoPE'd q/k hi/lo [b][h][s][d], q pre-scaled by 0.125
__device__ __nv_bfloat16 g_qh[(size_t)B_*H_*S_*DH_];
__device__ __nv_bfloat16 g_ql[(size_t)B_*H_*S_*DH_];
__device__ __nv_bfloat16 g_kh[(size_t)B_*H_*S_*DH_];
__device__ __nv_bfloat16 g_kl[(size_t)B_*H_*S_*DH_];
// V transposed hi/lo [b][h][d][s]
__device__ __nv_bfloat16 g_vth[(size_t)B_*H_*DH_*S_];
__device__ __nv_bfloat16 g_vtl[(size_t)B_*H_*DH_*S_];

// ---------------------------------------------------------------------------
// PTX helpers (sm_80-class only; compile at compute_103 base target)
// ---------------------------------------------------------------------------
__device__ __forceinline__ uint32_t smem_u32(const void* p) {
    uint32_t a;
    asm("{ .reg .u64 t; cvta.to.shared.u64 t, %1; cvt.u32.u64 %0, t; }"
        : "=r"(a) : "l"(p));
    return a;
}
__device__ __forceinline__ void cp_async16(uint32_t saddr, const void* gaddr) {
    asm volatile("cp.async.cg.shared.global [%0], [%1], 16;"
                 :: "r"(saddr), "l"(gaddr));
}
__device__ __forceinline__ void cp_commit() {
    asm volatile("cp.async.commit_group;");
}
template<int N>
__device__ __forceinline__ void cp_wait() {
    asm volatile("cp.async.wait_group %0;" :: "n"(N));
}
__device__ __forceinline__ void ldsm_x4(uint32_t* r, uint32_t addr) {
    asm volatile("ldmatrix.sync.aligned.m8n8.x4.shared.b16 {%0,%1,%2,%3}, [%4];"
                 : "=r"(r[0]), "=r"(r[1]), "=r"(r[2]), "=r"(r[3]) : "r"(addr));
}
__device__ __forceinline__ void ldsm_x2(uint32_t* r, uint32_t addr) {
    asm volatile("ldmatrix.sync.aligned.m8n8.x2.shared.b16 {%0,%1}, [%2];"
                 : "=r"(r[0]), "=r"(r[1]) : "r"(addr));
}
__device__ __forceinline__ void mma16816(float* d, const uint32_t* a,
                                         const uint32_t* b) {
    asm volatile(
        "mma.sync.aligned.m16n8k16.row.col.f32.bf16.bf16.f32 "
        "{%0,%1,%2,%3}, {%4,%5,%6,%7}, {%8,%9}, {%0,%1,%2,%3};"
        : "+f"(d[0]), "+f"(d[1]), "+f"(d[2]), "+f"(d[3])
        : "r"(a[0]), "r"(a[1]), "r"(a[2]), "r"(a[3]), "r"(b[0]), "r"(b[1]));
}
__device__ __forceinline__ uint32_t pack2bf(float a, float b) {
    __nv_bfloat162 h = __floats2bfloat162_rn(a, b);
    return *(uint32_t*)&h;
}

// ---------------------------------------------------------------------------
// Freq prep
// ---------------------------------------------------------------------------
__global__ void prep_freqs_kernel() {
    int i = threadIdx.x;
    if (i < 32) {
        g_freqs[i] = (float)exp(-(double)i * (9.210340371976184 / 32.0));
    }
}

// ---------------------------------------------------------------------------
// fp32 -> bf16 hi/lo split (4 floats per thread)
// ---------------------------------------------------------------------------
__global__ __launch_bounds__(256) void convert_hilo_kernel(
    const float* __restrict__ src, __nv_bfloat16* __restrict__ hi,
    __nv_bfloat16* __restrict__ lo)
{
    int i = (blockIdx.x * 256 + threadIdx.x) * 4;
    float4 v = *(const float4*)(src + i);
    __nv_bfloat16 h0 = __float2bfloat16(v.x);
    __nv_bfloat16 h1 = __float2bfloat16(v.y);
    __nv_bfloat16 h2 = __float2bfloat16(v.z);
    __nv_bfloat16 h3 = __float2bfloat16(v.w);
    __nv_bfloat16 l0 = __float2bfloat16(v.x - __bfloat162float(h0));
    __nv_bfloat16 l1 = __float2bfloat16(v.y - __bfloat162float(h1));
    __nv_bfloat16 l2 = __float2bfloat16(v.z - __bfloat162float(h2));
    __nv_bfloat16 l3 = __float2bfloat16(v.w - __bfloat162float(h3));
    *(__nv_bfloat162*)(hi + i)     = __halves2bfloat162(h0, h1);
    *(__nv_bfloat162*)(hi + i + 2) = __halves2bfloat162(h2, h3);
    *(__nv_bfloat162*)(lo + i)     = __halves2bfloat162(l0, l1);
    *(__nv_bfloat162*)(lo + i + 2) = __halves2bfloat162(l2, l3);
}

// ---------------------------------------------------------------------------
// Tensor-core GEMM via mma.sync bf16x3 (unchanged from R9)
// ---------------------------------------------------------------------------
#define STG_BYTES 32768
#define TCG_SMEM  65536

__device__ __forceinline__ void issue_tile(const __nv_bfloat16* __restrict__ g,
                                           int row0, int k0, uint32_t sbase,
                                           int tid) {
#pragma unroll
    for (int j = 0; j < 2; j++) {
        int idx = tid + j * 256;
        int r = idx >> 2, c = idx & 3;
        const void* gp = g + (size_t)(row0 + r) * 1024 + k0 + c * 8;
        uint32_t sp = sbase + r * 64 + ((c ^ ((r >> 1) & 3)) << 4);
        cp_async16(sp, gp);
    }
}

template<int MODE>
__global__ __launch_bounds__(256) void tc_gemm_kernel(
    const __nv_bfloat16* __restrict__ Ah, const __nv_bfloat16* __restrict__ Al,
    const __nv_bfloat16* __restrict__ Bh, const __nv_bfloat16* __restrict__ Bl,
    const float* __restrict__ bias, float* __restrict__ Cext, int N)
{
    extern __shared__ char smc[];
    const uint32_t sb = smem_u32(smc);
    const int tid  = threadIdx.x;
    const int lane = tid & 31;
    const int wid  = tid >> 5;
    const int wm   = wid >> 2;
    const int wn   = wid & 3;
    const int m0 = blockIdx.y * 128;
    const int n0 = blockIdx.x * 128;

    float acc[4][4][4];
#pragma unroll
    for (int mi = 0; mi < 4; mi++)
#pragma unroll
        for (int nj = 0; nj < 4; nj++)
#pragma unroll
            for (int e = 0; e < 4; e++) acc[mi][nj][e] = 0.0f;

    issue_tile(Ah, m0, 0, sb,         tid);
    issue_tile(Al, m0, 0, sb + 8192,  tid);
    issue_tile(Bh, n0, 0, sb + 16384, tid);
    issue_tile(Bl, n0, 0, sb + 24576, tid);
    cp_commit();

    int buf = 0;
    for (int it = 0; it < 32; it++) {
        if (it + 1 < 32) {
            uint32_t nb = sb + (buf ^ 1) * STG_BYTES;
            int k0 = (it + 1) * 32;
            issue_tile(Ah, m0, k0, nb,         tid);
            issue_tile(Al, m0, k0, nb + 8192,  tid);
            issue_tile(Bh, n0, k0, nb + 16384, tid);
            issue_tile(Bl, n0, k0, nb + 24576, tid);
            cp_commit();
            cp_wait<1>();
        } else {
            cp_wait<0>();
        }
        __syncthreads();

        const uint32_t sA = sb + buf * STG_BYTES;
#pragma unroll
        for (int ks = 0; ks < 2; ks++) {
            uint32_t ah[4][4], al[4][4], bh[4][2], bl[4][2];
#pragma unroll
            for (int mi = 0; mi < 4; mi++) {
                int row = wm * 64 + mi * 16 + (lane & 15);
                int ch  = ks * 2 + (lane >> 4);
                uint32_t ad = sA + row * 64 + ((ch ^ ((row >> 1) & 3)) << 4);
                ldsm_x4(ah[mi], ad);
                ldsm_x4(al[mi], ad + 8192);
            }
#pragma unroll
            for (int nj = 0; nj < 4; nj++) {
                int row = wn * 32 + nj * 8 + (lane & 7);
                int ch  = ks * 2 + ((lane >> 3) & 1);
                uint32_t bd = sA + 16384 + row * 64 + ((ch ^ ((row >> 1) & 3)) << 4);
                ldsm_x2(bh[nj], bd);
                ldsm_x2(bl[nj], bd + 8192);
            }
#pragma unroll
            for (int mi = 0; mi < 4; mi++)
#pragma unroll
                for (int nj = 0; nj < 4; nj++) {
                    mma16816(acc[mi][nj], ah[mi], bh[nj]);
                    mma16816(acc[mi][nj], al[mi], bh[nj]);
                    mma16816(acc[mi][nj], ah[mi], bl[nj]);
                }
        }
        __syncthreads();
        buf ^= 1;
    }

    const int gr = lane >> 2;
    const int gc = (lane & 3) * 2;
#pragma unroll
    for (int mi = 0; mi < 4; mi++) {
#pragma unroll
        for (int nj = 0; nj < 4; nj++) {
            int col = n0 + wn * 32 + nj * 8 + gc;
            float b0 = bias[col], b1 = bias[col + 1];
#pragma unroll
            for (int half = 0; half < 2; half++) {
                int row = m0 + wm * 64 + mi * 16 + gr + half * 8;
                float2 o;
                o.x = acc[mi][nj][half * 2 + 0] + b0;
                o.y = acc[mi][nj][half * 2 + 1] + b1;
                if (MODE == 1) {
                    *(float2*)(Cext + (size_t)row * N + col) = o;
                } else {
                    int i3  = col >> 10;
                    int rem = col & 1023;
                    int h   = rem >> 6;
                    int d   = rem & 63;
                    int b_  = row >> 11;
                    int s   = row & 2047;
                    float* base = (i3 == 0) ? g_q : (i3 == 1) ? g_k : g_v;
                    *(float2*)(base + ((size_t)((b_ * H_ + h) * S_) + s) * DH_ + d) = o;
                }
            }
        }
    }
}

// ---------------------------------------------------------------------------
// RoPE + bf16 hi/lo split. q scaled by 0.125 (exact). One thread per
// (b,h,s,d2<32); handles d2 and d2+32.
// ---------------------------------------------------------------------------
__global__ __launch_bounds__(256) void rope_split_kernel(const int* __restrict__ p) {
    int idx = blockIdx.x * 256 + threadIdx.x;
    int d2 = idx & 31;
    int s  = (idx >> 5) & 2047;
    int h  = (idx >> 16) & 15;
    int b  = idx >> 20;

    float f  = g_freqs[d2];
    float th = (float)p[b * S_ + s] * f;
    float sn, cs;
    sincosf(th, &sn, &cs);

    size_t base = ((size_t)((b * H_ + h) * S_) + s) * DH_;
    float q1 = g_q[base + d2], q2 = g_q[base + d2 + 32];
    float rq1 = (q1 * cs + q2 * sn) * SCALE_;
    float rq2 = (q2 * cs - q1 * sn) * SCALE_;
    float k1 = g_k[base + d2], k2 = g_k[base + d2 + 32];
    float rk1 = k1 * cs + k2 * sn;
    float rk2 = k2 * cs - k1 * sn;

    __nv_bfloat16 h1v = __float2bfloat16(rq1);
    __nv_bfloat16 h2v = __float2bfloat16(rq2);
    g_qh[base + d2]      = h1v;
    g_qh[base + d2 + 32] = h2v;
    g_ql[base + d2]      = __float2bfloat16(rq1 - __bfloat162float(h1v));
    g_ql[base + d2 + 32] = __float2bfloat16(rq2 - __bfloat162float(h2v));

    __nv_bfloat16 kh1 = __float2bfloat16(rk1);
    __nv_bfloat16 kh2 = __float2bfloat16(rk2);
    g_kh[base + d2]      = kh1;
    g_kh[base + d2 + 32] = kh2;
    g_kl[base + d2]      = __float2bfloat16(rk1 - __bfloat162float(kh1));
    g_kl[base + d2 + 32] = __float2bfloat16(rk2 - __bfloat162float(kh2));
}

// ---------------------------------------------------------------------------
// V transpose + split: g_v [b][h][s][d] fp32 -> g_vth/g_vtl [b][h][d][s] bf16
// grid (S/128, H, B), block 256.
// ---------------------------------------------------------------------------
__global__ __launch_bounds__(256) void vtrans_kernel() {
    __shared__ float tile[128][65];
    const int tid = threadIdx.x;
    const int st = blockIdx.x * 128;
    const int h  = blockIdx.y;
    const int b  = blockIdx.z;
    const size_t inb  = ((size_t)((b * H_ + h) * S_) + st) * DH_;
    const size_t outb = ((size_t)(b * H_ + h)) * DH_ * S_;

#pragma unroll
    for (int i = 0; i < 8; i++) {
        int idx = tid + i * 256;          // 128 rows x 16 float4
        int r = idx >> 4, c = idx & 15;
        float4 v = *(const float4*)(g_v + inb + (size_t)r * DH_ + c * 4);
        tile[r][c * 4 + 0] = v.x;
        tile[r][c * 4 + 1] = v.y;
        tile[r][c * 4 + 2] = v.z;
        tile[r][c * 4 + 3] = v.w;
    }
    __syncthreads();

#pragma unroll
    for (int i = 0; i < 8; i++) {
        int g = tid + i * 256;            // 64 d-rows x 32 s-groups(4)
        int d = g >> 5;
        int sc = (g & 31) * 4;
        float v0 = tile[sc + 0][d], v1 = tile[sc + 1][d];
        float v2 = tile[sc + 2][d], v3 = tile[sc + 3][d];
        __nv_bfloat16 h0 = __float2bfloat16(v0), h1 = __float2bfloat16(v1);
        __nv_bfloat16 h2 = __float2bfloat16(v2), h3 = __float2bfloat16(v3);
        uint2 hw, lw;
        hw.x = pack2bf(v0, v1); hw.y = pack2bf(v2, v3);
        lw.x = pack2bf(v0 - __bfloat162float(h0), v1 - __bfloat162float(h1));
        lw.y = pack2bf(v2 - __bfloat162float(h2), v3 - __bfloat162float(h3));
        size_t off = outb + (size_t)d * S_ + st + sc;
        *(uint2*)(g_vth + off) = hw;
        *(uint2*)(g_vtl + off) = lw;
    }
}

// ---------------------------------------------------------------------------
// Flash attention via mma.sync bf16x3.
// grid (S/128, H, B), block 256 (8 warps; warp w owns q rows [16w,16w+16)).
// Smem (dyn, 128KB): 2 buffers x { Kh 16K | Kl 16K | Vth 16K | Vtl 16K }.
// K rows: 128 x 128B, chunk swizzle c^(r&7). Vt rows: 64 x 256B, same swizzle.
// S frags: 16 n-tiles x 4; P repacked in-register to PV A-frags (FA2 style).
// ---------------------------------------------------------------------------
#define FLASH_SMEM 131072

__device__ __forceinline__ void flash_issue(int kt, uint32_t sbase,
                                            size_t kbase, size_t vtbase,
                                            int tid) {
#pragma unroll
    for (int i = 0; i < 4; i++) {
        int idx = tid + i * 256;          // 128 rows x 8 chunks
        int r = idx >> 3, c = idx & 7;
        size_t go = kbase + (size_t)(kt + r) * DH_ + c * 8;
        uint32_t sp = sbase + r * 128 + ((c ^ (r & 7)) << 4);
        cp_async16(sp, g_kh + go);
        cp_async16(sp + 16384, g_kl + go);
    }
#pragma unroll
    for (int i = 0; i < 4; i++) {
        int idx = tid + i * 256;          // 64 rows x 16 chunks
        int r = idx >> 4, c = idx & 15;
        size_t go = vtbase + (size_t)r * S_ + kt + c * 8;
        uint32_t sp = sbase + 32768 + r * 256 + ((c ^ (r & 7)) << 4);
        cp_async16(sp, g_vth + go);
        cp_async16(sp + 16384, g_vtl + go);
    }
}

__global__ __launch_bounds__(256) void flash_mma_kernel() {
    extern __shared__ char smf[];
    const uint32_t sb = smem_u32(smf);
    const int tid = threadIdx.x, lane = tid & 31, wq = tid >> 5;
    const int qb = blockIdx.x * 128;
    const int h  = blockIdx.y;
    const int b  = blockIdx.z;
    const size_t kbase  = ((size_t)(b * H_ + h)) * S_ * DH_;
    const size_t vtbase = ((size_t)(b * H_ + h)) * DH_ * S_;
    const int gr = lane >> 2, gc = (lane & 3) * 2;

    // Q fragments straight from gmem (pre-scaled, hi/lo)
    uint32_t qh[4][4], ql[4][4];
    {
        const __nv_bfloat16* qhp = g_qh + kbase + (size_t)(qb + wq * 16) * DH_;
        const __nv_bfloat16* qlp = g_ql + kbase + (size_t)(qb + wq * 16) * DH_;
#pragma unroll
        for (int ks = 0; ks < 4; ks++) {
            int c0 = ks * 16 + gc;
            qh[ks][0] = *(const uint32_t*)(qhp + gr * DH_ + c0);
            qh[ks][1] = *(const uint32_t*)(qhp + (gr + 8) * DH_ + c0);
            qh[ks][2] = *(const uint32_t*)(qhp + gr * DH_ + c0 + 8);
            qh[ks][3] = *(const uint32_t*)(qhp + (gr + 8) * DH_ + c0 + 8);
            ql[ks][0] = *(const uint32_t*)(qlp + gr * DH_ + c0);
            ql[ks][1] = *(const uint32_t*)(qlp + (gr + 8) * DH_ + c0);
            ql[ks][2] = *(const uint32_t*)(qlp + gr * DH_ + c0 + 8);
            ql[ks][3] = *(const uint32_t*)(qlp + (gr + 8) * DH_ + c0 + 8);
        }
    }

    float mr[2] = {-CUDART_INF_F, -CUDART_INF_F};
    float lr[2] = {0.0f, 0.0f};
    float o[8][4];
#pragma unroll
    for (int dt = 0; dt < 8; dt++)
#pragma unroll
        for (int e = 0; e < 4; e++) o[dt][e] = 0.0f;

    flash_issue(0, sb, kbase, vtbase, tid);
    cp_commit();

    for (int t = 0; t < 16; t++) {
        const int buf = t & 1;
        if (t + 1 < 16) {
            flash_issue((t + 1) * 128, sb + (buf ^ 1) * 65536, kbase, vtbase, tid);
            cp_commit();
            cp_wait<1>();
        } else {
            cp_wait<0>();
        }
        __syncthreads();

        const uint32_t ks_base = sb + buf * 65536;
        const uint32_t vs_base = ks_base + 32768;

        // ---- S = Q K^T (bf16x3) ----
        float sf[16][4];
#pragma unroll
        for (int nt = 0; nt < 16; nt++)
#pragma unroll
            for (int e = 0; e < 4; e++) sf[nt][e] = 0.0f;

#pragma unroll
        for (int nt = 0; nt < 16; nt++) {
            int row = nt * 8 + (lane & 7);
#pragma unroll
            for (int ks = 0; ks < 4; ks++) {
                int ch = (2 * ks + ((lane >> 3) & 1)) ^ (row & 7);
                uint32_t ad = ks_base + row * 128 + (ch << 4);
                uint32_t bh2[2], bl2[2];
                ldsm_x2(bh2, ad);
                ldsm_x2(bl2, ad + 16384);
                mma16816(sf[nt], qh[ks], bh2);
                mma16816(sf[nt], ql[ks], bh2);
                mma16816(sf[nt], qh[ks], bl2);
            }
        }

        // ---- online softmax (rows gr -> c0/c1, gr+8 -> c2/c3) ----
        {
            float mx0 = sf[0][0], mx1 = sf[0][2];
#pragma unroll
            for (int nt = 0; nt < 16; nt++) {
                mx0 = fmaxf(mx0, fmaxf(sf[nt][0], sf[nt][1]));
                mx1 = fmaxf(mx1, fmaxf(sf[nt][2], sf[nt][3]));
            }
            mx0 = fmaxf(mx0, __shfl_xor_sync(0xffffffffu, mx0, 1));
            mx0 = fmaxf(mx0, __shfl_xor_sync(0xffffffffu, mx0, 2));
            mx1 = fmaxf(mx1, __shfl_xor_sync(0xffffffffu, mx1, 1));
            mx1 = fmaxf(mx1, __shfl_xor_sync(0xffffffffu, mx1, 2));
            float mn0 = fmaxf(mr[0], mx0), mn1 = fmaxf(mr[1], mx1);
            float c0 = __expf(mr[0] - mn0), c1 = __expf(mr[1] - mn1);
            float s0 = 0.0f, s1 = 0.0f;
#pragma unroll
            for (int nt = 0; nt < 16; nt++) {
                sf[nt][0] = __expf(sf[nt][0] - mn0);
                sf[nt][1] = __expf(sf[nt][1] - mn0);
                sf[nt][2] = __expf(sf[nt][2] - mn1);
                sf[nt][3] = __expf(sf[nt][3] - mn1);
                s0 += sf[nt][0] + sf[nt][1];
                s1 += sf[nt][2] + sf[nt][3];
            }
            s0 += __shfl_xor_sync(0xffffffffu, s0, 1);
            s0 += __shfl_xor_sync(0xffffffffu, s0, 2);
            s1 += __shfl_xor_sync(0xffffffffu, s1, 1);
            s1 += __shfl_xor_sync(0xffffffffu, s1, 2);
            lr[0] = lr[0] * c0 + s0;
            lr[1] = lr[1] * c1 + s1;
            mr[0] = mn0; mr[1] = mn1;
#pragma unroll
            for (int dt = 0; dt < 8; dt++) {
                o[dt][0] *= c0; o[dt][1] *= c0;
                o[dt][2] *= c1; o[dt][3] *= c1;
            }
        }

        // ---- O += P V (bf16x3, P re-packed in registers) ----
#pragma unroll
        for (int js = 0; js < 8; js++) {
            uint32_t ah4[4], al4[4];
#pragma unroll
            for (int r = 0; r < 4; r++) {
                int tt = 2 * js + (r >> 1);
                int ci = (r & 1) * 2;
                float p0 = sf[tt][ci], p1 = sf[tt][ci + 1];
                __nv_bfloat16 h0 = __float2bfloat16(p0);
                __nv_bfloat16 h1 = __float2bfloat16(p1);
                __nv_bfloat162 hh = __halves2bfloat162(h0, h1);
                __nv_bfloat162 ll = __halves2bfloat162(
                    __float2bfloat16(p0 - __bfloat162float(h0)),
                    __float2bfloat16(p1 - __bfloat162float(h1)));
                ah4[r] = *(uint32_t*)&hh;
                al4[r] = *(uint32_t*)&ll;
            }
#pragma unroll
            for (int dt = 0; dt < 8; dt++) {
                int row = dt * 8 + (lane & 7);
                int ch = (2 * js + ((lane >> 3) & 1)) ^ (row & 7);
                uint32_t ad = vs_base + row * 256 + (ch << 4);
                uint32_t bh2[2], bl2[2];
                ldsm_x2(bh2, ad);
                ldsm_x2(bl2, ad + 16384);
                mma16816(o[dt], ah4, bh2);
                mma16816(o[dt], al4, bh2);
                mma16816(o[dt], ah4, bl2);
            }
        }
        __syncthreads();
    }

    // ---- epilogue: normalize, store to g_attn [B,S,D] ----
    float i0 = 1.0f / lr[0], i1 = 1.0f / lr[1];
    int s0r = qb + wq * 16 + gr;
    int s1r = s0r + 8;
#pragma unroll
    for (int dt = 0; dt < 8; dt++) {
        float2 oa, ob;
        oa.x = o[dt][0] * i0; oa.y = o[dt][1] * i0;
        ob.x = o[dt][2] * i1; ob.y = o[dt][3] * i1;
        *(float2*)(g_attn + ((size_t)(b * S_ + s0r)) * D_ + h * 64 + dt * 8 + gc) = oa;
        *(float2*)(g_attn + ((size_t)(b * S_ + s1r)) * D_ + h * 64 + dt * 8 + gc) = ob;
    }
}

// ---------------------------------------------------------------------------
// Launch
// ---------------------------------------------------------------------------
extern "C" void kernel_launch(void* const* d_in, const int* in_sizes, int n_in,
                              void* d_out, int out_size) {
    const float* x      = (const float*)d_in[0];
    const int*   p      = (const int*)d_in[1];
    const float* Wqkv_w = (const float*)d_in[2];
    const float* Wqkv_b = (const float*)d_in[3];
    const float* Wo_w   = (const float*)d_in[4];
    const float* Wo_b   = (const float*)d_in[5];
    float* out = (float*)d_out;

    cudaFuncSetAttribute(flash_mma_kernel,
                         cudaFuncAttributeMaxDynamicSharedMemorySize, FLASH_SMEM);
    cudaFuncSetAttribute(tc_gemm_kernel<0>,
                         cudaFuncAttributeMaxDynamicSharedMemorySize, TCG_SMEM);
    cudaFuncSetAttribute(tc_gemm_kernel<1>,
                         cudaFuncAttributeMaxDynamicSharedMemorySize, TCG_SMEM);

    __nv_bfloat16 *xh, *xl, *wqh, *wql, *aoh, *aol, *woh, *wol;
    cudaGetSymbolAddress((void**)&xh,  g_xh);
    cudaGetSymbolAddress((void**)&xl,  g_xl);
    cudaGetSymbolAddress((void**)&wqh, g_wqh);
    cudaGetSymbolAddress((void**)&wql, g_wql);
    cudaGetSymbolAddress((void**)&aoh, g_aoh);
    cudaGetSymbolAddress((void**)&aol, g_aol);
    cudaGetSymbolAddress((void**)&woh, g_woh);
    cudaGetSymbolAddress((void**)&wol, g_wol);
    float* attn;
    cudaGetSymbolAddress((void**)&attn, g_attn);

    // 0. Conversions + freqs
    convert_hilo_kernel<<<(B_ * S_ * D_) / 1024, 256>>>(x, xh, xl);
    convert_hilo_kernel<<<(3 * D_ * D_) / 1024, 256>>>(Wqkv_w, wqh, wql);
    convert_hilo_kernel<<<(D_ * D_) / 1024, 256>>>(Wo_w, woh, wol);
    prep_freqs_kernel<<<1, 32>>>();

    // 1. QKV projection (mma.sync bf16x3) -> g_q/g_k/g_v fp32
    tc_gemm_kernel<0><<<dim3(3 * D_ / 128, (B_ * S_) / 128), 256, TCG_SMEM>>>(
        xh, xl, wqh, wql, Wqkv_b, nullptr, 3 * D_);

    // 2. RoPE + hi/lo split; V transpose + split
    rope_split_kernel<<<(B_ * H_ * S_ * 32) / 256, 256>>>(p);
    vtrans_kernel<<<dim3(S_ / 128, H_, B_), 256>>>();

    // 3. Flash attention (mma.sync bf16x3) -> g_attn
    flash_mma_kernel<<<dim3(S_ / 128, H_, B_), 256, FLASH_SMEM>>>();

    // 4. Output projection
    convert_hilo_kernel<<<(B_ * S_ * D_) / 1024, 256>>>(attn, aoh, aol);
    tc_gemm_kernel<1><<<dim3(D_ / 128, (B_ * S_) / 128), 256, TCG_SMEM>>>(
        aoh, aol, woh, wol, Wo_b, out, D_);
}

// round 13
// speedup vs baseline: 3.7275x; 1.0272x over previous
#include <cuda_runtime.h>
#include <cuda_bf16.h>
#include <cstdint>
#include <math.h>
#include <math_constants.h>

#define B_  4
#define S_  2048
#define D_  1024
#define H_  16
#define DH_ 64
#define SCALE_ 0.125f

// ---------------------------------------------------------------------------
// Scratch (allocation-free rule: __device__ globals)
// ---------------------------------------------------------------------------
__device__ float g_q[(size_t)B_*H_*S_*DH_];
__device__ float g_k[(size_t)B_*H_*S_*DH_];
__device__ float g_freqs[32];

// bf16 hi/lo split operands
__device__ __nv_bfloat16 g_xh[(size_t)B_*S_*D_];
__device__ __nv_bfloat16 g_xl[(size_t)B_*S_*D_];
__device__ __nv_bfloat16 g_wqh[(size_t)3*D_*D_];
__device__ __nv_bfloat16 g_wql[(size_t)3*D_*D_];
__device__ __nv_bfloat16 g_aoh[(size_t)B_*S_*D_];
__device__ __nv_bfloat16 g_aol[(size_t)B_*S_*D_];
__device__ __nv_bfloat16 g_woh[(size_t)D_*D_];
__device__ __nv_bfloat16 g_wol[(size_t)D_*D_];
// RoPE'd q/k hi/lo [b][h][s][d], q pre-scaled by 0.125
__device__ __nv_bfloat16 g_qh[(size_t)B_*H_*S_*DH_];
__device__ __nv_bfloat16 g_ql[(size_t)B_*H_*S_*DH_];
__device__ __nv_bfloat16 g_kh[(size_t)B_*H_*S_*DH_];
__device__ __nv_bfloat16 g_kl[(size_t)B_*H_*S_*DH_];
// V hi/lo [b][h][s][d] (written directly by gemm<0> epilogue, post-bias)
__device__ __nv_bfloat16 g_vh[(size_t)B_*H_*S_*DH_];
__device__ __nv_bfloat16 g_vl[(size_t)B_*H_*S_*DH_];

// ---------------------------------------------------------------------------
// PTX helpers (sm_80-class only; compile at compute_103 base target)
// ---------------------------------------------------------------------------
__device__ __forceinline__ uint32_t smem_u32(const void* p) {
    uint32_t a;
    asm("{ .reg .u64 t; cvta.to.shared.u64 t, %1; cvt.u32.u64 %0, t; }"
        : "=r"(a) : "l"(p));
    return a;
}
__device__ __forceinline__ void cp_async16(uint32_t saddr, const void* gaddr) {
    asm volatile("cp.async.cg.shared.global [%0], [%1], 16;"
                 :: "r"(saddr), "l"(gaddr));
}
__device__ __forceinline__ void cp_commit() {
    asm volatile("cp.async.commit_group;");
}
template<int N>
__device__ __forceinline__ void cp_wait() {
    asm volatile("cp.async.wait_group %0;" :: "n"(N));
}
__device__ __forceinline__ void ldsm_x4(uint32_t* r, uint32_t addr) {
    asm volatile("ldmatrix.sync.aligned.m8n8.x4.shared.b16 {%0,%1,%2,%3}, [%4];"
                 : "=r"(r[0]), "=r"(r[1]), "=r"(r[2]), "=r"(r[3]) : "r"(addr));
}
__device__ __forceinline__ void ldsm_x2(uint32_t* r, uint32_t addr) {
    asm volatile("ldmatrix.sync.aligned.m8n8.x2.shared.b16 {%0,%1}, [%2];"
                 : "=r"(r[0]), "=r"(r[1]) : "r"(addr));
}
__device__ __forceinline__ void ldsm_x2_trans(uint32_t* r, uint32_t addr) {
    asm volatile("ldmatrix.sync.aligned.m8n8.x2.trans.shared.b16 {%0,%1}, [%2];"
                 : "=r"(r[0]), "=r"(r[1]) : "r"(addr));
}
__device__ __forceinline__ void mma16816(float* d, const uint32_t* a,
                                         const uint32_t* b) {
    asm volatile(
        "mma.sync.aligned.m16n8k16.row.col.f32.bf16.bf16.f32 "
        "{%0,%1,%2,%3}, {%4,%5,%6,%7}, {%8,%9}, {%0,%1,%2,%3};"
        : "+f"(d[0]), "+f"(d[1]), "+f"(d[2]), "+f"(d[3])
        : "r"(a[0]), "r"(a[1]), "r"(a[2]), "r"(a[3]), "r"(b[0]), "r"(b[1]));
}

// ---------------------------------------------------------------------------
// Freq prep
// ---------------------------------------------------------------------------
__global__ void prep_freqs_kernel() {
    int i = threadIdx.x;
    if (i < 32) {
        g_freqs[i] = (float)exp(-(double)i * (9.210340371976184 / 32.0));
    }
}

// ---------------------------------------------------------------------------
// fp32 -> bf16 hi/lo split (4 floats per thread)
// ---------------------------------------------------------------------------
__global__ __launch_bounds__(256) void convert_hilo_kernel(
    const float* __restrict__ src, __nv_bfloat16* __restrict__ hi,
    __nv_bfloat16* __restrict__ lo)
{
    int i = (blockIdx.x * 256 + threadIdx.x) * 4;
    float4 v = *(const float4*)(src + i);
    __nv_bfloat16 h0 = __float2bfloat16(v.x);
    __nv_bfloat16 h1 = __float2bfloat16(v.y);
    __nv_bfloat16 h2 = __float2bfloat16(v.z);
    __nv_bfloat16 h3 = __float2bfloat16(v.w);
    __nv_bfloat16 l0 = __float2bfloat16(v.x - __bfloat162float(h0));
    __nv_bfloat16 l1 = __float2bfloat16(v.y - __bfloat162float(h1));
    __nv_bfloat16 l2 = __float2bfloat16(v.z - __bfloat162float(h2));
    __nv_bfloat16 l3 = __float2bfloat16(v.w - __bfloat162float(h3));
    *(__nv_bfloat162*)(hi + i)     = __halves2bfloat162(h0, h1);
    *(__nv_bfloat162*)(hi + i + 2) = __halves2bfloat162(h2, h3);
    *(__nv_bfloat162*)(lo + i)     = __halves2bfloat162(l0, l1);
    *(__nv_bfloat162*)(lo + i + 2) = __halves2bfloat162(l2, l3);
}

// ---------------------------------------------------------------------------
// Tensor-core GEMM via mma.sync bf16x3: C = (Ah+Al)(Bh+Bl)^T + bias
// Tile BM=128, BN=128, BK=32; 8 warps (2m x 4n), warp 64x32; 3-stage cp.async.
// MODE 0: q/k -> fp32 g_q/g_k; v -> bf16 hi/lo g_vh/g_vl (split post-bias).
// MODE 1: bias+store fp32 to Cext.
// ---------------------------------------------------------------------------
#define STG_BYTES 32768
#define TCG_SMEM  98304   // 3 stages

__device__ __forceinline__ void issue_tile(const __nv_bfloat16* __restrict__ g,
                                           int row0, int k0, uint32_t sbase,
                                           int tid) {
#pragma unroll
    for (int j = 0; j < 2; j++) {
        int idx = tid + j * 256;
        int r = idx >> 2, c = idx & 3;
        const void* gp = g + (size_t)(row0 + r) * 1024 + k0 + c * 8;
        uint32_t sp = sbase + r * 64 + ((c ^ ((r >> 1) & 3)) << 4);
        cp_async16(sp, gp);
    }
}

template<int MODE>
__global__ __launch_bounds__(256) void tc_gemm_kernel(
    const __nv_bfloat16* __restrict__ Ah, const __nv_bfloat16* __restrict__ Al,
    const __nv_bfloat16* __restrict__ Bh, const __nv_bfloat16* __restrict__ Bl,
    const float* __restrict__ bias, float* __restrict__ Cext, int N)
{
    extern __shared__ char smc[];
    const uint32_t sb = smem_u32(smc);
    const int tid  = threadIdx.x;
    const int lane = tid & 31;
    const int wid  = tid >> 5;
    const int wm   = wid >> 2;
    const int wn   = wid & 3;
    const int m0 = blockIdx.y * 128;
    const int n0 = blockIdx.x * 128;

    float acc[4][4][4];
#pragma unroll
    for (int mi = 0; mi < 4; mi++)
#pragma unroll
        for (int nj = 0; nj < 4; nj++)
#pragma unroll
            for (int e = 0; e < 4; e++) acc[mi][nj][e] = 0.0f;

    // Preload stages 0,1
#pragma unroll
    for (int ps = 0; ps < 2; ps++) {
        uint32_t bbase = sb + ps * STG_BYTES;
        issue_tile(Ah, m0, ps * 32, bbase,         tid);
        issue_tile(Al, m0, ps * 32, bbase + 8192,  tid);
        issue_tile(Bh, n0, ps * 32, bbase + 16384, tid);
        issue_tile(Bl, n0, ps * 32, bbase + 24576, tid);
        cp_commit();
    }

    for (int it = 0; it < 32; it++) {
        if (it + 2 < 32) {
            uint32_t nb = sb + ((it + 2) % 3) * STG_BYTES;
            int k0 = (it + 2) * 32;
            issue_tile(Ah, m0, k0, nb,         tid);
            issue_tile(Al, m0, k0, nb + 8192,  tid);
            issue_tile(Bh, n0, k0, nb + 16384, tid);
            issue_tile(Bl, n0, k0, nb + 24576, tid);
        }
        cp_commit();
        cp_wait<2>();
        __syncthreads();

        const uint32_t sA = sb + (it % 3) * STG_BYTES;
#pragma unroll
        for (int ks = 0; ks < 2; ks++) {
            uint32_t ah[4][4], al[4][4], bh[4][2], bl[4][2];
#pragma unroll
            for (int mi = 0; mi < 4; mi++) {
                int row = wm * 64 + mi * 16 + (lane & 15);
                int ch  = ks * 2 + (lane >> 4);
                uint32_t ad = sA + row * 64 + ((ch ^ ((row >> 1) & 3)) << 4);
                ldsm_x4(ah[mi], ad);
                ldsm_x4(al[mi], ad + 8192);
            }
#pragma unroll
            for (int nj = 0; nj < 4; nj++) {
                int row = wn * 32 + nj * 8 + (lane & 7);
                int ch  = ks * 2 + ((lane >> 3) & 1);
                uint32_t bd = sA + 16384 + row * 64 + ((ch ^ ((row >> 1) & 3)) << 4);
                ldsm_x2(bh[nj], bd);
                ldsm_x2(bl[nj], bd + 8192);
            }
#pragma unroll
            for (int mi = 0; mi < 4; mi++)
#pragma unroll
                for (int nj = 0; nj < 4; nj++) {
                    mma16816(acc[mi][nj], ah[mi], bh[nj]);
                    mma16816(acc[mi][nj], al[mi], bh[nj]);
                    mma16816(acc[mi][nj], ah[mi], bl[nj]);
                }
        }
        __syncthreads();
    }

    const int gr = lane >> 2;
    const int gc = (lane & 3) * 2;
#pragma unroll
    for (int mi = 0; mi < 4; mi++) {
#pragma unroll
        for (int nj = 0; nj < 4; nj++) {
            int col = n0 + wn * 32 + nj * 8 + gc;
            float b0 = bias[col], b1 = bias[col + 1];
#pragma unroll
            for (int half = 0; half < 2; half++) {
                int row = m0 + wm * 64 + mi * 16 + gr + half * 8;
                float2 o;
                o.x = acc[mi][nj][half * 2 + 0] + b0;
                o.y = acc[mi][nj][half * 2 + 1] + b1;
                if (MODE == 1) {
                    *(float2*)(Cext + (size_t)row * N + col) = o;
                } else {
                    int i3  = col >> 10;
                    int rem = col & 1023;
                    int h   = rem >> 6;
                    int d   = rem & 63;
                    int b_  = row >> 11;
                    int s   = row & 2047;
                    size_t off = ((size_t)((b_ * H_ + h) * S_) + s) * DH_ + d;
                    if (i3 == 2) {
                        __nv_bfloat16 h0 = __float2bfloat16(o.x);
                        __nv_bfloat16 h1 = __float2bfloat16(o.y);
                        __nv_bfloat162 hh = __halves2bfloat162(h0, h1);
                        __nv_bfloat162 ll = __halves2bfloat162(
                            __float2bfloat16(o.x - __bfloat162float(h0)),
                            __float2bfloat16(o.y - __bfloat162float(h1)));
                        *(uint32_t*)(g_vh + off) = *(uint32_t*)&hh;
                        *(uint32_t*)(g_vl + off) = *(uint32_t*)&ll;
                    } else {
                        float* base = (i3 == 0) ? g_q : g_k;
                        *(float2*)(base + off) = o;
                    }
                }
            }
        }
    }
}

// ---------------------------------------------------------------------------
// RoPE + bf16 hi/lo split. q scaled by 0.125 (exact).
// ---------------------------------------------------------------------------
__global__ __launch_bounds__(256) void rope_split_kernel(const int* __restrict__ p) {
    int idx = blockIdx.x * 256 + threadIdx.x;
    int d2 = idx & 31;
    int s  = (idx >> 5) & 2047;
    int h  = (idx >> 16) & 15;
    int b  = idx >> 20;

    float f  = g_freqs[d2];
    float th = (float)p[b * S_ + s] * f;
    float sn, cs;
    sincosf(th, &sn, &cs);

    size_t base = ((size_t)((b * H_ + h) * S_) + s) * DH_;
    float q1 = g_q[base + d2], q2 = g_q[base + d2 + 32];
    float rq1 = (q1 * cs + q2 * sn) * SCALE_;
    float rq2 = (q2 * cs - q1 * sn) * SCALE_;
    float k1 = g_k[base + d2], k2 = g_k[base + d2 + 32];
    float rk1 = k1 * cs + k2 * sn;
    float rk2 = k2 * cs - k1 * sn;

    __nv_bfloat16 h1v = __float2bfloat16(rq1);
    __nv_bfloat16 h2v = __float2bfloat16(rq2);
    g_qh[base + d2]      = h1v;
    g_qh[base + d2 + 32] = h2v;
    g_ql[base + d2]      = __float2bfloat16(rq1 - __bfloat162float(h1v));
    g_ql[base + d2 + 32] = __float2bfloat16(rq2 - __bfloat162float(h2v));

    __nv_bfloat16 kh1 = __float2bfloat16(rk1);
    __nv_bfloat16 kh2 = __float2bfloat16(rk2);
    g_kh[base + d2]      = kh1;
    g_kh[base + d2 + 32] = kh2;
    g_kl[base + d2]      = __float2bfloat16(rk1 - __bfloat162float(kh1));
    g_kl[base + d2 + 32] = __float2bfloat16(rk2 - __bfloat162float(kh2));
}

// ---------------------------------------------------------------------------
// Flash attention via mma.sync bf16x3, 3-stage pipeline.
// grid (S/128, H, B), 256 thr (8 warps; warp w owns q rows [16w,16w+16)).
// Stage (64KB): Kh 16K | Kl 16K | Vh 16K | Vl 16K -- all rows [s][d] 128B,
// chunk swizzle c^(r&7). PV B-frags via ldmatrix.trans on V[j][d].
// Output written as bf16 hi/lo directly to g_aoh/g_aol.
// ---------------------------------------------------------------------------
#define FLASH_SMEM 196608   // 3 stages x 64KB

__device__ __forceinline__ void flash_issue(int kt, uint32_t sbase,
                                            size_t base, int tid) {
#pragma unroll
    for (int i = 0; i < 4; i++) {
        int idx = tid + i * 256;          // 128 rows x 8 chunks
        int r = idx >> 3, c = idx & 7;
        size_t go = base + (size_t)(kt + r) * DH_ + c * 8;
        uint32_t sp = sbase + r * 128 + ((c ^ (r & 7)) << 4);
        cp_async16(sp,         g_kh + go);
        cp_async16(sp + 16384, g_kl + go);
        cp_async16(sp + 32768, g_vh + go);
        cp_async16(sp + 49152, g_vl + go);
    }
}

__global__ __launch_bounds__(256) void flash_mma_kernel() {
    extern __shared__ char smf[];
    const uint32_t sb = smem_u32(smf);
    const int tid = threadIdx.x, lane = tid & 31, wq = tid >> 5;
    const int qb = blockIdx.x * 128;
    const int h  = blockIdx.y;
    const int b  = blockIdx.z;
    const size_t kbase = ((size_t)(b * H_ + h)) * S_ * DH_;
    const int gr = lane >> 2, gc = (lane & 3) * 2;

    // Q fragments straight from gmem (pre-scaled, hi/lo)
    uint32_t qh[4][4], ql[4][4];
    {
        const __nv_bfloat16* qhp = g_qh + kbase + (size_t)(qb + wq * 16) * DH_;
        const __nv_bfloat16* qlp = g_ql + kbase + (size_t)(qb + wq * 16) * DH_;
#pragma unroll
        for (int ks = 0; ks < 4; ks++) {
            int c0 = ks * 16 + gc;
            qh[ks][0] = *(const uint32_t*)(qhp + gr * DH_ + c0);
            qh[ks][1] = *(const uint32_t*)(qhp + (gr + 8) * DH_ + c0);
            qh[ks][2] = *(const uint32_t*)(qhp + gr * DH_ + c0 + 8);
            qh[ks][3] = *(const uint32_t*)(qhp + (gr + 8) * DH_ + c0 + 8);
            ql[ks][0] = *(const uint32_t*)(qlp + gr * DH_ + c0);
            ql[ks][1] = *(const uint32_t*)(qlp + (gr + 8) * DH_ + c0);
            ql[ks][2] = *(const uint32_t*)(qlp + gr * DH_ + c0 + 8);
            ql[ks][3] = *(const uint32_t*)(qlp + (gr + 8) * DH_ + c0 + 8);
        }
    }

    float mr[2] = {-CUDART_INF_F, -CUDART_INF_F};
    float lr[2] = {0.0f, 0.0f};
    float o[8][4];
#pragma unroll
    for (int dt = 0; dt < 8; dt++)
#pragma unroll
        for (int e = 0; e < 4; e++) o[dt][e] = 0.0f;

    // Preload stages 0,1
    flash_issue(0, sb, kbase, tid);
    cp_commit();
    flash_issue(128, sb + 65536, kbase, tid);
    cp_commit();

    for (int t = 0; t < 16; t++) {
        if (t + 2 < 16) {
            flash_issue((t + 2) * 128, sb + ((t + 2) % 3) * 65536, kbase, tid);
        }
        cp_commit();
        cp_wait<2>();
        __syncthreads();

        const uint32_t ks_base = sb + (t % 3) * 65536;
        const uint32_t vs_base = ks_base + 32768;

        // ---- S = Q K^T (bf16x3) ----
        float sf[16][4];
#pragma unroll
        for (int nt = 0; nt < 16; nt++)
#pragma unroll
            for (int e = 0; e < 4; e++) sf[nt][e] = 0.0f;

#pragma unroll
        for (int nt = 0; nt < 16; nt++) {
            int row = nt * 8 + (lane & 7);
#pragma unroll
            for (int ks = 0; ks < 4; ks++) {
                int ch = (2 * ks + ((lane >> 3) & 1)) ^ (row & 7);
                uint32_t ad = ks_base + row * 128 + (ch << 4);
                uint32_t bh2[2], bl2[2];
                ldsm_x2(bh2, ad);
                ldsm_x2(bl2, ad + 16384);
                mma16816(sf[nt], qh[ks], bh2);
                mma16816(sf[nt], ql[ks], bh2);
                mma16816(sf[nt], qh[ks], bl2);
            }
        }

        // ---- online softmax ----
        {
            float mx0 = sf[0][0], mx1 = sf[0][2];
#pragma unroll
            for (int nt = 0; nt < 16; nt++) {
                mx0 = fmaxf(mx0, fmaxf(sf[nt][0], sf[nt][1]));
                mx1 = fmaxf(mx1, fmaxf(sf[nt][2], sf[nt][3]));
            }
            mx0 = fmaxf(mx0, __shfl_xor_sync(0xffffffffu, mx0, 1));
            mx0 = fmaxf(mx0, __shfl_xor_sync(0xffffffffu, mx0, 2));
            mx1 = fmaxf(mx1, __shfl_xor_sync(0xffffffffu, mx1, 1));
            mx1 = fmaxf(mx1, __shfl_xor_sync(0xffffffffu, mx1, 2));
            float mn0 = fmaxf(mr[0], mx0), mn1 = fmaxf(mr[1], mx1);
            float c0 = __expf(mr[0] - mn0), c1 = __expf(mr[1] - mn1);
            float s0 = 0.0f, s1 = 0.0f;
#pragma unroll
            for (int nt = 0; nt < 16; nt++) {
                sf[nt][0] = __expf(sf[nt][0] - mn0);
                sf[nt][1] = __expf(sf[nt][1] - mn0);
                sf[nt][2] = __expf(sf[nt][2] - mn1);
                sf[nt][3] = __expf(sf[nt][3] - mn1);
                s0 += sf[nt][0] + sf[nt][1];
                s1 += sf[nt][2] + sf[nt][3];
            }
            s0 += __shfl_xor_sync(0xffffffffu, s0, 1);
            s0 += __shfl_xor_sync(0xffffffffu, s0, 2);
            s1 += __shfl_xor_sync(0xffffffffu, s1, 1);
            s1 += __shfl_xor_sync(0xffffffffu, s1, 2);
            lr[0] = lr[0] * c0 + s0;
            lr[1] = lr[1] * c1 + s1;
            mr[0] = mn0; mr[1] = mn1;
#pragma unroll
            for (int dt = 0; dt < 8; dt++) {
                o[dt][0] *= c0; o[dt][1] *= c0;
                o[dt][2] *= c1; o[dt][3] *= c1;
            }
        }

        // ---- O += P V (bf16x3; V frags via ldmatrix.trans on [j][d]) ----
#pragma unroll
        for (int js = 0; js < 8; js++) {
            uint32_t ah4[4], al4[4];
#pragma unroll
            for (int r = 0; r < 4; r++) {
                int tt = 2 * js + (r >> 1);
                int ci = (r & 1) * 2;
                float p0 = sf[tt][ci], p1 = sf[tt][ci + 1];
                __nv_bfloat16 h0 = __float2bfloat16(p0);
                __nv_bfloat16 h1 = __float2bfloat16(p1);
                __nv_bfloat162 hh = __halves2bfloat162(h0, h1);
                __nv_bfloat162 ll = __halves2bfloat162(
                    __float2bfloat16(p0 - __bfloat162float(h0)),
                    __float2bfloat16(p1 - __bfloat162float(h1)));
                ah4[r] = *(uint32_t*)&hh;
                al4[r] = *(uint32_t*)&ll;
            }
            int vrow = js * 16 + (lane & 15);
#pragma unroll
            for (int dt = 0; dt < 8; dt++) {
                int ch = dt ^ (vrow & 7);
                uint32_t ad = vs_base + vrow * 128 + (ch << 4);
                uint32_t bh2[2], bl2[2];
                ldsm_x2_trans(bh2, ad);
                ldsm_x2_trans(bl2, ad + 16384);
                mma16816(o[dt], ah4, bh2);
                mma16816(o[dt], al4, bh2);
                mma16816(o[dt], ah4, bl2);
            }
        }
        __syncthreads();
    }

    // ---- epilogue: normalize, hi/lo split, store to g_aoh/g_aol ----
    float i0 = 1.0f / lr[0], i1 = 1.0f / lr[1];
    int s0r = qb + wq * 16 + gr;
    int s1r = s0r + 8;
#pragma unroll
    for (int dt = 0; dt < 8; dt++) {
        float a0 = o[dt][0] * i0, a1 = o[dt][1] * i0;
        float b0 = o[dt][2] * i1, b1 = o[dt][3] * i1;
        size_t offA = ((size_t)(b * S_ + s0r)) * D_ + h * 64 + dt * 8 + gc;
        size_t offB = ((size_t)(b * S_ + s1r)) * D_ + h * 64 + dt * 8 + gc;
        __nv_bfloat16 ha0 = __float2bfloat16(a0), ha1 = __float2bfloat16(a1);
        __nv_bfloat16 hb0 = __float2bfloat16(b0), hb1 = __float2bfloat16(b1);
        __nv_bfloat162 hA = __halves2bfloat162(ha0, ha1);
        __nv_bfloat162 hB = __halves2bfloat162(hb0, hb1);
        __nv_bfloat162 lA = __halves2bfloat162(
            __float2bfloat16(a0 - __bfloat162float(ha0)),
            __float2bfloat16(a1 - __bfloat162float(ha1)));
        __nv_bfloat162 lB = __halves2bfloat162(
            __float2bfloat16(b0 - __bfloat162float(hb0)),
            __float2bfloat16(b1 - __bfloat162float(hb1)));
        *(uint32_t*)(g_aoh + offA) = *(uint32_t*)&hA;
        *(uint32_t*)(g_aoh + offB) = *(uint32_t*)&hB;
        *(uint32_t*)(g_aol + offA) = *(uint32_t*)&lA;
        *(uint32_t*)(g_aol + offB) = *(uint32_t*)&lB;
    }
}

// ---------------------------------------------------------------------------
// Launch  (gemm<0> placed 4th: the profiler captures the 4th launch)
// ---------------------------------------------------------------------------
extern "C" void kernel_launch(void* const* d_in, const int* in_sizes, int n_in,
                              void* d_out, int out_size) {
    const float* x      = (const float*)d_in[0];
    const int*   p      = (const int*)d_in[1];
    const float* Wqkv_w = (const float*)d_in[2];
    const float* Wqkv_b = (const float*)d_in[3];
    const float* Wo_w   = (const float*)d_in[4];
    const float* Wo_b   = (const float*)d_in[5];
    float* out = (float*)d_out;

    cudaFuncSetAttribute(flash_mma_kernel,
                         cudaFuncAttributeMaxDynamicSharedMemorySize, FLASH_SMEM);
    cudaFuncSetAttribute(tc_gemm_kernel<0>,
                         cudaFuncAttributeMaxDynamicSharedMemorySize, TCG_SMEM);
    cudaFuncSetAttribute(tc_gemm_kernel<1>,
                         cudaFuncAttributeMaxDynamicSharedMemorySize, TCG_SMEM);

    __nv_bfloat16 *xh, *xl, *wqh, *wql, *aoh, *aol, *woh, *wol;
    cudaGetSymbolAddress((void**)&xh,  g_xh);
    cudaGetSymbolAddress((void**)&xl,  g_xl);
    cudaGetSymbolAddress((void**)&wqh, g_wqh);
    cudaGetSymbolAddress((void**)&wql, g_wql);
    cudaGetSymbolAddress((void**)&aoh, g_aoh);
    cudaGetSymbolAddress((void**)&aol, g_aol);
    cudaGetSymbolAddress((void**)&woh, g_woh);
    cudaGetSymbolAddress((void**)&wol, g_wol);

    // 1-3. input conversions + freqs
    convert_hilo_kernel<<<(B_ * S_ * D_) / 1024, 256>>>(x, xh, xl);
    convert_hilo_kernel<<<(3 * D_ * D_) / 1024, 256>>>(Wqkv_w, wqh, wql);
    prep_freqs_kernel<<<1, 32>>>();

    // 4. QKV projection -> g_q/g_k fp32, g_vh/g_vl bf16
    tc_gemm_kernel<0><<<dim3(3 * D_ / 128, (B_ * S_) / 128), 256, TCG_SMEM>>>(
        xh, xl, wqh, wql, Wqkv_b, nullptr, 3 * D_);

    // 5. RoPE + hi/lo split
    rope_split_kernel<<<(B_ * H_ * S_ * 32) / 256, 256>>>(p);

    // 6. Flash attention -> g_aoh/g_aol bf16
    flash_mma_kernel<<<dim3(S_ / 128, H_, B_), 256, FLASH_SMEM>>>();

    // 7-8. Wo conversion + output projection
    convert_hilo_kernel<<<(D_ * D_) / 1024, 256>>>(Wo_w, woh, wol);
    tc_gemm_kernel<1><<<dim3(D_ / 128, (B_ * S_) / 128), 256, TCG_SMEM>>>(
        aoh, aol, woh, wol, Wo_b, out, D_);
}

// round 14
// speedup vs baseline: 5.1727x; 1.3877x over previous
#include <cuda_runtime.h>
#include <cuda_fp16.h>
#include <cstdint>
#include <math.h>
#include <math_constants.h>

#define B_  4
#define S_  2048
#define D_  1024
#define H_  16
#define DH_ 64
#define SCALE_ 0.125f

// ---------------------------------------------------------------------------
// Scratch (allocation-free rule: __device__ globals)
// ---------------------------------------------------------------------------
__device__ float g_q[(size_t)B_*H_*S_*DH_];
__device__ float g_k[(size_t)B_*H_*S_*DH_];
__device__ float g_freqs[32];

// fp16 operands (one-sided hi/lo split on A operands; B operands single fp16)
__device__ __half g_xh[(size_t)B_*S_*D_];
__device__ __half g_xl[(size_t)B_*S_*D_];
__device__ __half g_wq[(size_t)3*D_*D_];
__device__ __half g_aoh[(size_t)B_*S_*D_];
__device__ __half g_aol[(size_t)B_*S_*D_];
__device__ __half g_wo[(size_t)D_*D_];
// RoPE'd q hi/lo (pre-scaled by 0.125), k single fp16  [b][h][s][d]
__device__ __half g_qh[(size_t)B_*H_*S_*DH_];
__device__ __half g_ql[(size_t)B_*H_*S_*DH_];
__device__ __half g_kh[(size_t)B_*H_*S_*DH_];
// V single fp16 [b][h][s][d] (written by gemm<0> epilogue, post-bias)
__device__ __half g_vh[(size_t)B_*H_*S_*DH_];

// ---------------------------------------------------------------------------
// PTX helpers (sm_80-class only; compile at compute_103 base target)
// ---------------------------------------------------------------------------
__device__ __forceinline__ uint32_t smem_u32(const void* p) {
    uint32_t a;
    asm("{ .reg .u64 t; cvta.to.shared.u64 t, %1; cvt.u32.u64 %0, t; }"
        : "=r"(a) : "l"(p));
    return a;
}
__device__ __forceinline__ void cp_async16(uint32_t saddr, const void* gaddr) {
    asm volatile("cp.async.cg.shared.global [%0], [%1], 16;"
                 :: "r"(saddr), "l"(gaddr));
}
__device__ __forceinline__ void cp_commit() {
    asm volatile("cp.async.commit_group;");
}
template<int N>
__device__ __forceinline__ void cp_wait() {
    asm volatile("cp.async.wait_group %0;" :: "n"(N));
}
__device__ __forceinline__ void ldsm_x4(uint32_t* r, uint32_t addr) {
    asm volatile("ldmatrix.sync.aligned.m8n8.x4.shared.b16 {%0,%1,%2,%3}, [%4];"
                 : "=r"(r[0]), "=r"(r[1]), "=r"(r[2]), "=r"(r[3]) : "r"(addr));
}
__device__ __forceinline__ void ldsm_x2(uint32_t* r, uint32_t addr) {
    asm volatile("ldmatrix.sync.aligned.m8n8.x2.shared.b16 {%0,%1}, [%2];"
                 : "=r"(r[0]), "=r"(r[1]) : "r"(addr));
}
__device__ __forceinline__ void ldsm_x2_trans(uint32_t* r, uint32_t addr) {
    asm volatile("ldmatrix.sync.aligned.m8n8.x2.trans.shared.b16 {%0,%1}, [%2];"
                 : "=r"(r[0]), "=r"(r[1]) : "r"(addr));
}
__device__ __forceinline__ void mma16816(float* d, const uint32_t* a,
                                         const uint32_t* b) {
    asm volatile(
        "mma.sync.aligned.m16n8k16.row.col.f32.f16.f16.f32 "
        "{%0,%1,%2,%3}, {%4,%5,%6,%7}, {%8,%9}, {%0,%1,%2,%3};"
        : "+f"(d[0]), "+f"(d[1]), "+f"(d[2]), "+f"(d[3])
        : "r"(a[0]), "r"(a[1]), "r"(a[2]), "r"(a[3]), "r"(b[0]), "r"(b[1]));
}
__device__ __forceinline__ uint32_t pack2h(float a, float b) {
    __half2 h = __floats2half2_rn(a, b);
    return *(uint32_t*)&h;
}

// ---------------------------------------------------------------------------
// Freq prep
// ---------------------------------------------------------------------------
__global__ void prep_freqs_kernel() {
    int i = threadIdx.x;
    if (i < 32) {
        g_freqs[i] = (float)exp(-(double)i * (9.210340371976184 / 32.0));
    }
}

// ---------------------------------------------------------------------------
// fp32 -> fp16 hi/lo split (4 floats per thread)
// ---------------------------------------------------------------------------
__global__ __launch_bounds__(256) void convert_hilo_kernel(
    const float* __restrict__ src, __half* __restrict__ hi,
    __half* __restrict__ lo)
{
    int i = (blockIdx.x * 256 + threadIdx.x) * 4;
    float4 v = *(const float4*)(src + i);
    __half h0 = __float2half_rn(v.x);
    __half h1 = __float2half_rn(v.y);
    __half h2 = __float2half_rn(v.z);
    __half h3 = __float2half_rn(v.w);
    *(__half2*)(hi + i)     = __halves2half2(h0, h1);
    *(__half2*)(hi + i + 2) = __halves2half2(h2, h3);
    *(uint32_t*)(lo + i)     = pack2h(v.x - __half2float(h0), v.y - __half2float(h1));
    *(uint32_t*)(lo + i + 2) = pack2h(v.z - __half2float(h2), v.w - __half2float(h3));
}

// fp32 -> fp16 single
__global__ __launch_bounds__(256) void convert_single_kernel(
    const float* __restrict__ src, __half* __restrict__ dst)
{
    int i = (blockIdx.x * 256 + threadIdx.x) * 4;
    float4 v = *(const float4*)(src + i);
    *(uint32_t*)(dst + i)     = pack2h(v.x, v.y);
    *(uint32_t*)(dst + i + 2) = pack2h(v.z, v.w);
}

// ---------------------------------------------------------------------------
// Tensor-core GEMM, fp16x2: C = (Ah+Al)[M,K] @ (B16[N,K])^T + bias
// Tile BM=128, BN=128, BK=32; 8 warps (2m x 4n), warp 64x32; 3-stage cp.async.
// Stage: Ah 8K | Al 8K | B 8K.
// MODE 0: q/k -> fp32 g_q/g_k; v -> fp16 g_vh (post-bias).
// MODE 1: bias+store fp32 to Cext.
// ---------------------------------------------------------------------------
#define STG_BYTES 24576
#define TCG_SMEM  73728   // 3 stages

__device__ __forceinline__ void issue_tile(const __half* __restrict__ g,
                                           int row0, int k0, uint32_t sbase,
                                           int tid) {
#pragma unroll
    for (int j = 0; j < 2; j++) {
        int idx = tid + j * 256;
        int r = idx >> 2, c = idx & 3;
        const void* gp = g + (size_t)(row0 + r) * 1024 + k0 + c * 8;
        uint32_t sp = sbase + r * 64 + ((c ^ ((r >> 1) & 3)) << 4);
        cp_async16(sp, gp);
    }
}

template<int MODE>
__global__ __launch_bounds__(256) void tc_gemm_kernel(
    const __half* __restrict__ Ah, const __half* __restrict__ Al,
    const __half* __restrict__ Bw,
    const float* __restrict__ bias, float* __restrict__ Cext, int N)
{
    extern __shared__ char smc[];
    const uint32_t sb = smem_u32(smc);
    const int tid  = threadIdx.x;
    const int lane = tid & 31;
    const int wid  = tid >> 5;
    const int wm   = wid >> 2;
    const int wn   = wid & 3;
    const int m0 = blockIdx.y * 128;
    const int n0 = blockIdx.x * 128;

    float acc[4][4][4];
#pragma unroll
    for (int mi = 0; mi < 4; mi++)
#pragma unroll
        for (int nj = 0; nj < 4; nj++)
#pragma unroll
            for (int e = 0; e < 4; e++) acc[mi][nj][e] = 0.0f;

#pragma unroll
    for (int ps = 0; ps < 2; ps++) {
        uint32_t bbase = sb + ps * STG_BYTES;
        issue_tile(Ah, m0, ps * 32, bbase,         tid);
        issue_tile(Al, m0, ps * 32, bbase + 8192,  tid);
        issue_tile(Bw, n0, ps * 32, bbase + 16384, tid);
        cp_commit();
    }

    for (int it = 0; it < 32; it++) {
        if (it + 2 < 32) {
            uint32_t nb = sb + ((it + 2) % 3) * STG_BYTES;
            int k0 = (it + 2) * 32;
            issue_tile(Ah, m0, k0, nb,         tid);
            issue_tile(Al, m0, k0, nb + 8192,  tid);
            issue_tile(Bw, n0, k0, nb + 16384, tid);
        }
        cp_commit();
        cp_wait<2>();
        __syncthreads();

        const uint32_t sA = sb + (it % 3) * STG_BYTES;
#pragma unroll
        for (int ks = 0; ks < 2; ks++) {
            uint32_t ah[4][4], al[4][4], bh[4][2];
#pragma unroll
            for (int mi = 0; mi < 4; mi++) {
                int row = wm * 64 + mi * 16 + (lane & 15);
                int ch  = ks * 2 + (lane >> 4);
                uint32_t ad = sA + row * 64 + ((ch ^ ((row >> 1) & 3)) << 4);
                ldsm_x4(ah[mi], ad);
                ldsm_x4(al[mi], ad + 8192);
            }
#pragma unroll
            for (int nj = 0; nj < 4; nj++) {
                int row = wn * 32 + nj * 8 + (lane & 7);
                int ch  = ks * 2 + ((lane >> 3) & 1);
                uint32_t bd = sA + 16384 + row * 64 + ((ch ^ ((row >> 1) & 3)) << 4);
                ldsm_x2(bh[nj], bd);
            }
#pragma unroll
            for (int mi = 0; mi < 4; mi++)
#pragma unroll
                for (int nj = 0; nj < 4; nj++) {
                    mma16816(acc[mi][nj], ah[mi], bh[nj]);
                    mma16816(acc[mi][nj], al[mi], bh[nj]);
                }
        }
        __syncthreads();
    }

    const int gr = lane >> 2;
    const int gc = (lane & 3) * 2;
#pragma unroll
    for (int mi = 0; mi < 4; mi++) {
#pragma unroll
        for (int nj = 0; nj < 4; nj++) {
            int col = n0 + wn * 32 + nj * 8 + gc;
            float b0 = bias[col], b1 = bias[col + 1];
#pragma unroll
            for (int half = 0; half < 2; half++) {
                int row = m0 + wm * 64 + mi * 16 + gr + half * 8;
                float2 o;
                o.x = acc[mi][nj][half * 2 + 0] + b0;
                o.y = acc[mi][nj][half * 2 + 1] + b1;
                if (MODE == 1) {
                    *(float2*)(Cext + (size_t)row * N + col) = o;
                } else {
                    int i3  = col >> 10;
                    int rem = col & 1023;
                    int h   = rem >> 6;
                    int d   = rem & 63;
                    int b_  = row >> 11;
                    int s   = row & 2047;
                    size_t off = ((size_t)((b_ * H_ + h) * S_) + s) * DH_ + d;
                    if (i3 == 2) {
                        *(uint32_t*)(g_vh + off) = pack2h(o.x, o.y);
                    } else {
                        float* base = (i3 == 0) ? g_q : g_k;
                        *(float2*)(base + off) = o;
                    }
                }
            }
        }
    }
}

// ---------------------------------------------------------------------------
// RoPE + fp16 conversion. q hi/lo (scaled by 0.125, exact), k single fp16.
// ---------------------------------------------------------------------------
__global__ __launch_bounds__(256) void rope_split_kernel(const int* __restrict__ p) {
    int idx = blockIdx.x * 256 + threadIdx.x;
    int d2 = idx & 31;
    int s  = (idx >> 5) & 2047;
    int h  = (idx >> 16) & 15;
    int b  = idx >> 20;

    float f  = g_freqs[d2];
    float th = (float)p[b * S_ + s] * f;
    float sn, cs;
    sincosf(th, &sn, &cs);

    size_t base = ((size_t)((b * H_ + h) * S_) + s) * DH_;
    float q1 = g_q[base + d2], q2 = g_q[base + d2 + 32];
    float rq1 = (q1 * cs + q2 * sn) * SCALE_;
    float rq2 = (q2 * cs - q1 * sn) * SCALE_;
    float k1 = g_k[base + d2], k2 = g_k[base + d2 + 32];

    __half h1v = __float2half_rn(rq1);
    __half h2v = __float2half_rn(rq2);
    g_qh[base + d2]      = h1v;
    g_qh[base + d2 + 32] = h2v;
    g_ql[base + d2]      = __float2half_rn(rq1 - __half2float(h1v));
    g_ql[base + d2 + 32] = __float2half_rn(rq2 - __half2float(h2v));

    g_kh[base + d2]      = __float2half_rn(k1 * cs + k2 * sn);
    g_kh[base + d2 + 32] = __float2half_rn(k2 * cs - k1 * sn);
}

// ---------------------------------------------------------------------------
// Flash attention, fp16x2, 3-stage pipeline.
// grid (S/128, H, B), 256 thr (8 warps; warp w owns q rows [16w,16w+16)).
// Stage (32KB): K 16K | V 16K, rows [s][d] 128B, chunk swizzle c^(r&7).
// QK: Q hi/lo (regs) x K single.  PV: P hi/lo (regs) x V single (ldsm.trans).
// Output bf-split... fp16 hi/lo direct to g_aoh/g_aol.
// ---------------------------------------------------------------------------
#define FLASH_SMEM 98304   // 3 stages x 32KB

__device__ __forceinline__ void flash_issue(int kt, uint32_t sbase,
                                            size_t base, int tid) {
#pragma unroll
    for (int i = 0; i < 4; i++) {
        int idx = tid + i * 256;          // 128 rows x 8 chunks
        int r = idx >> 3, c = idx & 7;
        size_t go = base + (size_t)(kt + r) * DH_ + c * 8;
        uint32_t sp = sbase + r * 128 + ((c ^ (r & 7)) << 4);
        cp_async16(sp,         g_kh + go);
        cp_async16(sp + 16384, g_vh + go);
    }
}

__global__ __launch_bounds__(256) void flash_mma_kernel() {
    extern __shared__ char smf[];
    const uint32_t sb = smem_u32(smf);
    const int tid = threadIdx.x, lane = tid & 31, wq = tid >> 5;
    const int qb = blockIdx.x * 128;
    const int h  = blockIdx.y;
    const int b  = blockIdx.z;
    const size_t kbase = ((size_t)(b * H_ + h)) * S_ * DH_;
    const int gr = lane >> 2, gc = (lane & 3) * 2;

    // Q fragments straight from gmem (pre-scaled, hi/lo fp16)
    uint32_t qh[4][4], ql[4][4];
    {
        const __half* qhp = g_qh + kbase + (size_t)(qb + wq * 16) * DH_;
        const __half* qlp = g_ql + kbase + (size_t)(qb + wq * 16) * DH_;
#pragma unroll
        for (int ks = 0; ks < 4; ks++) {
            int c0 = ks * 16 + gc;
            qh[ks][0] = *(const uint32_t*)(qhp + gr * DH_ + c0);
            qh[ks][1] = *(const uint32_t*)(qhp + (gr + 8) * DH_ + c0);
            qh[ks][2] = *(const uint32_t*)(qhp + gr * DH_ + c0 + 8);
            qh[ks][3] = *(const uint32_t*)(qhp + (gr + 8) * DH_ + c0 + 8);
            ql[ks][0] = *(const uint32_t*)(qlp + gr * DH_ + c0);
            ql[ks][1] = *(const uint32_t*)(qlp + (gr + 8) * DH_ + c0);
            ql[ks][2] = *(const uint32_t*)(qlp + gr * DH_ + c0 + 8);
            ql[ks][3] = *(const uint32_t*)(qlp + (gr + 8) * DH_ + c0 + 8);
        }
    }

    float mr[2] = {-CUDART_INF_F, -CUDART_INF_F};
    float lr[2] = {0.0f, 0.0f};
    float o[8][4];
#pragma unroll
    for (int dt = 0; dt < 8; dt++)
#pragma unroll
        for (int e = 0; e < 4; e++) o[dt][e] = 0.0f;

    flash_issue(0, sb, kbase, tid);
    cp_commit();
    flash_issue(128, sb + 32768, kbase, tid);
    cp_commit();

    for (int t = 0; t < 16; t++) {
        if (t + 2 < 16) {
            flash_issue((t + 2) * 128, sb + ((t + 2) % 3) * 32768, kbase, tid);
        }
        cp_commit();
        cp_wait<2>();
        __syncthreads();

        const uint32_t ks_base = sb + (t % 3) * 32768;
        const uint32_t vs_base = ks_base + 16384;

        // ---- S = Q K^T (fp16x2) ----
        float sf[16][4];
#pragma unroll
        for (int nt = 0; nt < 16; nt++)
#pragma unroll
            for (int e = 0; e < 4; e++) sf[nt][e] = 0.0f;

#pragma unroll
        for (int nt = 0; nt < 16; nt++) {
            int row = nt * 8 + (lane & 7);
#pragma unroll
            for (int ks = 0; ks < 4; ks++) {
                int ch = (2 * ks + ((lane >> 3) & 1)) ^ (row & 7);
                uint32_t ad = ks_base + row * 128 + (ch << 4);
                uint32_t kf[2];
                ldsm_x2(kf, ad);
                mma16816(sf[nt], qh[ks], kf);
                mma16816(sf[nt], ql[ks], kf);
            }
        }

        // ---- online softmax ----
        {
            float mx0 = sf[0][0], mx1 = sf[0][2];
#pragma unroll
            for (int nt = 0; nt < 16; nt++) {
                mx0 = fmaxf(mx0, fmaxf(sf[nt][0], sf[nt][1]));
                mx1 = fmaxf(mx1, fmaxf(sf[nt][2], sf[nt][3]));
            }
            mx0 = fmaxf(mx0, __shfl_xor_sync(0xffffffffu, mx0, 1));
            mx0 = fmaxf(mx0, __shfl_xor_sync(0xffffffffu, mx0, 2));
            mx1 = fmaxf(mx1, __shfl_xor_sync(0xffffffffu, mx1, 1));
            mx1 = fmaxf(mx1, __shfl_xor_sync(0xffffffffu, mx1, 2));
            float mn0 = fmaxf(mr[0], mx0), mn1 = fmaxf(mr[1], mx1);
            float c0 = __expf(mr[0] - mn0), c1 = __expf(mr[1] - mn1);
            float s0 = 0.0f, s1 = 0.0f;
#pragma unroll
            for (int nt = 0; nt < 16; nt++) {
                sf[nt][0] = __expf(sf[nt][0] - mn0);
                sf[nt][1] = __expf(sf[nt][1] - mn0);
                sf[nt][2] = __expf(sf[nt][2] - mn1);
                sf[nt][3] = __expf(sf[nt][3] - mn1);
                s0 += sf[nt][0] + sf[nt][1];
                s1 += sf[nt][2] + sf[nt][3];
            }
            s0 += __shfl_xor_sync(0xffffffffu, s0, 1);
            s0 += __shfl_xor_sync(0xffffffffu, s0, 2);
            s1 += __shfl_xor_sync(0xffffffffu, s1, 1);
            s1 += __shfl_xor_sync(0xffffffffu, s1, 2);
            lr[0] = lr[0] * c0 + s0;
            lr[1] = lr[1] * c1 + s1;
            mr[0] = mn0; mr[1] = mn1;
#pragma unroll
            for (int dt = 0; dt < 8; dt++) {
                o[dt][0] *= c0; o[dt][1] *= c0;
                o[dt][2] *= c1; o[dt][3] *= c1;
            }
        }

        // ---- O += P V (fp16x2; V frags via ldmatrix.trans on [j][d]) ----
#pragma unroll
        for (int js = 0; js < 8; js++) {
            uint32_t ph4[4], pl4[4];
#pragma unroll
            for (int r = 0; r < 4; r++) {
                int tt = 2 * js + (r >> 1);
                int ci = (r & 1) * 2;
                float p0 = sf[tt][ci], p1 = sf[tt][ci + 1];
                __half h0 = __float2half_rn(p0);
                __half h1 = __float2half_rn(p1);
                __half2 hh = __halves2half2(h0, h1);
                ph4[r] = *(uint32_t*)&hh;
                pl4[r] = pack2h(p0 - __half2float(h0), p1 - __half2float(h1));
            }
            int vrow = js * 16 + (lane & 15);
#pragma unroll
            for (int dt = 0; dt < 8; dt++) {
                int ch = dt ^ (vrow & 7);
                uint32_t ad = vs_base + vrow * 128 + (ch << 4);
                uint32_t vf[2];
                ldsm_x2_trans(vf, ad);
                mma16816(o[dt], ph4, vf);
                mma16816(o[dt], pl4, vf);
            }
        }
        __syncthreads();
    }

    // ---- epilogue: normalize, fp16 hi/lo split, store to g_aoh/g_aol ----
    float i0 = 1.0f / lr[0], i1 = 1.0f / lr[1];
    int s0r = qb + wq * 16 + gr;
    int s1r = s0r + 8;
#pragma unroll
    for (int dt = 0; dt < 8; dt++) {
        float a0 = o[dt][0] * i0, a1 = o[dt][1] * i0;
        float b0 = o[dt][2] * i1, b1 = o[dt][3] * i1;
        size_t offA = ((size_t)(b * S_ + s0r)) * D_ + h * 64 + dt * 8 + gc;
        size_t offB = ((size_t)(b * S_ + s1r)) * D_ + h * 64 + dt * 8 + gc;
        __half ha0 = __float2half_rn(a0), ha1 = __float2half_rn(a1);
        __half hb0 = __float2half_rn(b0), hb1 = __float2half_rn(b1);
        __half2 hA = __halves2half2(ha0, ha1);
        __half2 hB = __halves2half2(hb0, hb1);
        *(uint32_t*)(g_aoh + offA) = *(uint32_t*)&hA;
        *(uint32_t*)(g_aoh + offB) = *(uint32_t*)&hB;
        *(uint32_t*)(g_aol + offA) =
            pack2h(a0 - __half2float(ha0), a1 - __half2float(ha1));
        *(uint32_t*)(g_aol + offB) =
            pack2h(b0 - __half2float(hb0), b1 - __half2float(hb1));
    }
}

// ---------------------------------------------------------------------------
// Launch  (gemm<0> stays 4th: the profiler captures the 4th launch)
// ---------------------------------------------------------------------------
extern "C" void kernel_launch(void* const* d_in, const int* in_sizes, int n_in,
                              void* d_out, int out_size) {
    const float* x      = (const float*)d_in[0];
    const int*   p      = (const int*)d_in[1];
    const float* Wqkv_w = (const float*)d_in[2];
    const float* Wqkv_b = (const float*)d_in[3];
    const float* Wo_w   = (const float*)d_in[4];
    const float* Wo_b   = (const float*)d_in[5];
    float* out = (float*)d_out;

    cudaFuncSetAttribute(flash_mma_kernel,
                         cudaFuncAttributeMaxDynamicSharedMemorySize, FLASH_SMEM);
    cudaFuncSetAttribute(tc_gemm_kernel<0>,
                         cudaFuncAttributeMaxDynamicSharedMemorySize, TCG_SMEM);
    cudaFuncSetAttribute(tc_gemm_kernel<1>,
                         cudaFuncAttributeMaxDynamicSharedMemorySize, TCG_SMEM);

    __half *xh, *xl, *wq, *aoh, *aol, *wo;
    cudaGetSymbolAddress((void**)&xh,  g_xh);
    cudaGetSymbolAddress((void**)&xl,  g_xl);
    cudaGetSymbolAddress((void**)&wq,  g_wq);
    cudaGetSymbolAddress((void**)&aoh, g_aoh);
    cudaGetSymbolAddress((void**)&aol, g_aol);
    cudaGetSymbolAddress((void**)&wo,  g_wo);

    // 1-3. input conversions + freqs
    convert_hilo_kernel<<<(B_ * S_ * D_) / 1024, 256>>>(x, xh, xl);
    convert_single_kernel<<<(3 * D_ * D_) / 1024, 256>>>(Wqkv_w, wq);
    prep_freqs_kernel<<<1, 32>>>();

    // 4. QKV projection -> g_q/g_k fp32, g_vh fp16
    tc_gemm_kernel<0><<<dim3(3 * D_ / 128, (B_ * S_) / 128), 256, TCG_SMEM>>>(
        xh, xl, wq, Wqkv_b, nullptr, 3 * D_);

    // 5. RoPE + fp16 conversion
    rope_split_kernel<<<(B_ * H_ * S_ * 32) / 256, 256>>>(p);

    // 6. Flash attention -> g_aoh/g_aol fp16
    flash_mma_kernel<<<dim3(S_ / 128, H_, B_), 256, FLASH_SMEM>>>();

    // 7-8. Wo conversion + output projection
    convert_single_kernel<<<(D_ * D_) / 1024, 256>>>(Wo_w, wo);
    tc_gemm_kernel<1><<<dim3(D_ / 128, (B_ * S_) / 128), 256, TCG_SMEM>>>(
        aoh, aol, wo, Wo_b, out, D_);
}

// round 16
// speedup vs baseline: 8.1445x; 1.5745x over previous
#include <cuda_runtime.h>
#include <cuda_fp16.h>
#include <cstdint>
#include <math.h>
#include <math_constants.h>

#define B_  4
#define S_  2048
#define D_  1024
#define H_  16
#define DH_ 64
#define SCALE_ 0.125f

// ---------------------------------------------------------------------------
// Scratch (allocation-free rule: __device__ globals)
// ---------------------------------------------------------------------------
__device__ float g_q[(size_t)B_*H_*S_*DH_];
__device__ float g_k[(size_t)B_*H_*S_*DH_];
__device__ float g_freqs[32];

// fp16 single-precision operands everywhere
__device__ __half g_x16[(size_t)B_*S_*D_];
__device__ __half g_wq[(size_t)3*D_*D_];
__device__ __half g_ao[(size_t)B_*S_*D_];
__device__ __half g_wo[(size_t)D_*D_];
// RoPE'd q (pre-scaled by 0.125) / k, fp16 [b][h][s][d]
__device__ __half g_qh[(size_t)B_*H_*S_*DH_];
__device__ __half g_kh[(size_t)B_*H_*S_*DH_];
// V fp16 [b][h][s][d] (written by gemm<0> epilogue, post-bias)
__device__ __half g_vh[(size_t)B_*H_*S_*DH_];

// ---------------------------------------------------------------------------
// PTX helpers (sm_80-class only; compile at compute_103 base target)
// ---------------------------------------------------------------------------
__device__ __forceinline__ uint32_t smem_u32(const void* p) {
    uint32_t a;
    asm("{ .reg .u64 t; cvta.to.shared.u64 t, %1; cvt.u32.u64 %0, t; }"
        : "=r"(a) : "l"(p));
    return a;
}
__device__ __forceinline__ void cp_async16(uint32_t saddr, const void* gaddr) {
    asm volatile("cp.async.cg.shared.global [%0], [%1], 16;"
                 :: "r"(saddr), "l"(gaddr));
}
__device__ __forceinline__ void cp_commit() {
    asm volatile("cp.async.commit_group;");
}
template<int N>
__device__ __forceinline__ void cp_wait() {
    asm volatile("cp.async.wait_group %0;" :: "n"(N));
}
__device__ __forceinline__ void ldsm_x4(uint32_t* r, uint32_t addr) {
    asm volatile("ldmatrix.sync.aligned.m8n8.x4.shared.b16 {%0,%1,%2,%3}, [%4];"
                 : "=r"(r[0]), "=r"(r[1]), "=r"(r[2]), "=r"(r[3]) : "r"(addr));
}
__device__ __forceinline__ void ldsm_x2(uint32_t* r, uint32_t addr) {
    asm volatile("ldmatrix.sync.aligned.m8n8.x2.shared.b16 {%0,%1}, [%2];"
                 : "=r"(r[0]), "=r"(r[1]) : "r"(addr));
}
__device__ __forceinline__ void ldsm_x2_trans(uint32_t* r, uint32_t addr) {
    asm volatile("ldmatrix.sync.aligned.m8n8.x2.trans.shared.b16 {%0,%1}, [%2];"
                 : "=r"(r[0]), "=r"(r[1]) : "r"(addr));
}
__device__ __forceinline__ void mma16816(float* d, const uint32_t* a,
                                         const uint32_t* b) {
    asm volatile(
        "mma.sync.aligned.m16n8k16.row.col.f32.f16.f16.f32 "
        "{%0,%1,%2,%3}, {%4,%5,%6,%7}, {%8,%9}, {%0,%1,%2,%3};"
        : "+f"(d[0]), "+f"(d[1]), "+f"(d[2]), "+f"(d[3])
        : "r"(a[0]), "r"(a[1]), "r"(a[2]), "r"(a[3]), "r"(b[0]), "r"(b[1]));
}
__device__ __forceinline__ uint32_t pack2h(float a, float b) {
    __half2 h = __floats2half2_rn(a, b);
    return *(uint32_t*)&h;
}

// ---------------------------------------------------------------------------
// Freq prep
// ---------------------------------------------------------------------------
__global__ void prep_freqs_kernel() {
    int i = threadIdx.x;
    if (i < 32) {
        g_freqs[i] = (float)exp(-(double)i * (9.210340371976184 / 32.0));
    }
}

// ---------------------------------------------------------------------------
// fp32 -> fp16 (4 floats per thread)
// ---------------------------------------------------------------------------
__global__ __launch_bounds__(256) void convert_single_kernel(
    const float* __restrict__ src, __half* __restrict__ dst)
{
    int i = (blockIdx.x * 256 + threadIdx.x) * 4;
    float4 v = *(const float4*)(src + i);
    *(uint32_t*)(dst + i)     = pack2h(v.x, v.y);
    *(uint32_t*)(dst + i + 2) = pack2h(v.z, v.w);
}

// ---------------------------------------------------------------------------
// Tensor-core GEMM, fp16 single: C = A16[M,K] @ (B16[N,K])^T + bias
// Tile BM=128, BN=128, BK=32; 8 warps (2m x 4n), warp 64x32; 3-stage cp.async.
// Stage: A 8K | B 8K.
// MODE 0: q/k -> fp32 g_q/g_k; v -> fp16 g_vh (post-bias).
// MODE 1: bias+store fp32 to Cext.
// ---------------------------------------------------------------------------
#define STG_BYTES 16384
#define TCG_SMEM  49152   // 3 stages

__device__ __forceinline__ void issue_tile(const __half* __restrict__ g,
                                           int row0, int k0, uint32_t sbase,
                                           int tid) {
#pragma unroll
    for (int j = 0; j < 2; j++) {
        int idx = tid + j * 256;
        int r = idx >> 2, c = idx & 3;
        const void* gp = g + (size_t)(row0 + r) * 1024 + k0 + c * 8;
        uint32_t sp = sbase + r * 64 + ((c ^ ((r >> 1) & 3)) << 4);
        cp_async16(sp, gp);
    }
}

template<int MODE>
__global__ __launch_bounds__(256) void tc_gemm_kernel(
    const __half* __restrict__ Aw, const __half* __restrict__ Bw,
    const float* __restrict__ bias, float* __restrict__ Cext, int N)
{
    extern __shared__ char smc[];
    const uint32_t sb = smem_u32(smc);
    const int tid  = threadIdx.x;
    const int lane = tid & 31;
    const int wid  = tid >> 5;
    const int wm   = wid >> 2;
    const int wn   = wid & 3;
    const int m0 = blockIdx.y * 128;
    const int n0 = blockIdx.x * 128;

    float acc[4][4][4];
#pragma unroll
    for (int mi = 0; mi < 4; mi++)
#pragma unroll
        for (int nj = 0; nj < 4; nj++)
#pragma unroll
            for (int e = 0; e < 4; e++) acc[mi][nj][e] = 0.0f;

#pragma unroll
    for (int ps = 0; ps < 2; ps++) {
        uint32_t bbase = sb + ps * STG_BYTES;
        issue_tile(Aw, m0, ps * 32, bbase,        tid);
        issue_tile(Bw, n0, ps * 32, bbase + 8192, tid);
        cp_commit();
    }

    for (int it = 0; it < 32; it++) {
        if (it + 2 < 32) {
            uint32_t nb = sb + ((it + 2) % 3) * STG_BYTES;
            int k0 = (it + 2) * 32;
            issue_tile(Aw, m0, k0, nb,        tid);
            issue_tile(Bw, n0, k0, nb + 8192, tid);
        }
        cp_commit();
        cp_wait<2>();
        __syncthreads();

        const uint32_t sA = sb + (it % 3) * STG_BYTES;
#pragma unroll
        for (int ks = 0; ks < 2; ks++) {
            uint32_t ah[4][4], bh[4][2];
#pragma unroll
            for (int mi = 0; mi < 4; mi++) {
                int row = wm * 64 + mi * 16 + (lane & 15);
                int ch  = ks * 2 + (lane >> 4);
                uint32_t ad = sA + row * 64 + ((ch ^ ((row >> 1) & 3)) << 4);
                ldsm_x4(ah[mi], ad);
            }
#pragma unroll
            for (int nj = 0; nj < 4; nj++) {
                int row = wn * 32 + nj * 8 + (lane & 7);
                int ch  = ks * 2 + ((lane >> 3) & 1);
                uint32_t bd = sA + 8192 + row * 64 + ((ch ^ ((row >> 1) & 3)) << 4);
                ldsm_x2(bh[nj], bd);
            }
#pragma unroll
            for (int mi = 0; mi < 4; mi++)
#pragma unroll
                for (int nj = 0; nj < 4; nj++)
                    mma16816(acc[mi][nj], ah[mi], bh[nj]);
        }
        __syncthreads();
    }

    const int gr = lane >> 2;
    const int gc = (lane & 3) * 2;
#pragma unroll
    for (int mi = 0; mi < 4; mi++) {
#pragma unroll
        for (int nj = 0; nj < 4; nj++) {
            int col = n0 + wn * 32 + nj * 8 + gc;
            float b0 = bias[col], b1 = bias[col + 1];
#pragma unroll
            for (int half = 0; half < 2; half++) {
                int row = m0 + wm * 64 + mi * 16 + gr + half * 8;
                float2 o;
                o.x = acc[mi][nj][half * 2 + 0] + b0;
                o.y = acc[mi][nj][half * 2 + 1] + b1;
                if (MODE == 1) {
                    *(float2*)(Cext + (size_t)row * N + col) = o;
                } else {
                    int i3  = col >> 10;
                    int rem = col & 1023;
                    int h   = rem >> 6;
                    int d   = rem & 63;
                    int b_  = row >> 11;
                    int s   = row & 2047;
                    size_t off = ((size_t)((b_ * H_ + h) * S_) + s) * DH_ + d;
                    if (i3 == 2) {
                        *(uint32_t*)(g_vh + off) = pack2h(o.x, o.y);
                    } else {
                        float* base = (i3 == 0) ? g_q : g_k;
                        *(float2*)(base + off) = o;
                    }
                }
            }
        }
    }
}

// ---------------------------------------------------------------------------
// RoPE + fp16 conversion. q scaled by 0.125 (exact), k single fp16.
// ---------------------------------------------------------------------------
__global__ __launch_bounds__(256) void rope_split_kernel(const int* __restrict__ p) {
    int idx = blockIdx.x * 256 + threadIdx.x;
    int d2 = idx & 31;
    int s  = (idx >> 5) & 2047;
    int h  = (idx >> 16) & 15;
    int b  = idx >> 20;

    float f  = g_freqs[d2];
    float th = (float)p[b * S_ + s] * f;
    float sn, cs;
    sincosf(th, &sn, &cs);

    size_t base = ((size_t)((b * H_ + h) * S_) + s) * DH_;
    float q1 = g_q[base + d2], q2 = g_q[base + d2 + 32];
    float k1 = g_k[base + d2], k2 = g_k[base + d2 + 32];

    g_qh[base + d2]      = __float2half_rn((q1 * cs + q2 * sn) * SCALE_);
    g_qh[base + d2 + 32] = __float2half_rn((q2 * cs - q1 * sn) * SCALE_);
    g_kh[base + d2]      = __float2half_rn(k1 * cs + k2 * sn);
    g_kh[base + d2 + 32] = __float2half_rn(k2 * cs - k1 * sn);
}

// ---------------------------------------------------------------------------
// Flash attention, fp16 single, 3-stage pipeline.
// grid (S/128, H, B), 256 thr (8 warps; warp w owns q rows [16w,16w+16)).
// Stage (32KB): K 16K | V 16K, rows [s][d] 128B, chunk swizzle c^(r&7).
// QK: ks-outer/nt-inner (acc chain distance 16).  PV: V via ldsm.trans.
// Output fp16 direct to g_ao.
// ---------------------------------------------------------------------------
#define FLASH_SMEM 98304   // 3 stages x 32KB

__device__ __forceinline__ void flash_issue(int kt, uint32_t sbase,
                                            size_t base, int tid) {
#pragma unroll
    for (int i = 0; i < 4; i++) {
        int idx = tid + i * 256;          // 128 rows x 8 chunks
        int r = idx >> 3, c = idx & 7;
        size_t go = base + (size_t)(kt + r) * DH_ + c * 8;
        uint32_t sp = sbase + r * 128 + ((c ^ (r & 7)) << 4);
        cp_async16(sp,         g_kh + go);
        cp_async16(sp + 16384, g_vh + go);
    }
}

__global__ __launch_bounds__(256) void flash_mma_kernel() {
    extern __shared__ char smf[];
    const uint32_t sb = smem_u32(smf);
    const int tid = threadIdx.x, lane = tid & 31, wq = tid >> 5;
    const int qb = blockIdx.x * 128;
    const int h  = blockIdx.y;
    const int b  = blockIdx.z;
    const size_t kbase = ((size_t)(b * H_ + h)) * S_ * DH_;
    const int gr = lane >> 2, gc = (lane & 3) * 2;

    // Q fragments straight from gmem (pre-scaled fp16)
    uint32_t qh[4][4];
    {
        const __half* qhp = g_qh + kbase + (size_t)(qb + wq * 16) * DH_;
#pragma unroll
        for (int ks = 0; ks < 4; ks++) {
            int c0 = ks * 16 + gc;
            qh[ks][0] = *(const uint32_t*)(qhp + gr * DH_ + c0);
            qh[ks][1] = *(const uint32_t*)(qhp + (gr + 8) * DH_ + c0);
            qh[ks][2] = *(const uint32_t*)(qhp + gr * DH_ + c0 + 8);
            qh[ks][3] = *(const uint32_t*)(qhp + (gr + 8) * DH_ + c0 + 8);
        }
    }

    float mr[2] = {-CUDART_INF_F, -CUDART_INF_F};
    float lr[2] = {0.0f, 0.0f};
    float o[8][4];
#pragma unroll
    for (int dt = 0; dt < 8; dt++)
#pragma unroll
        for (int e = 0; e < 4; e++) o[dt][e] = 0.0f;

    flash_issue(0, sb, kbase, tid);
    cp_commit();
    flash_issue(128, sb + 32768, kbase, tid);
    cp_commit();

    for (int t = 0; t < 16; t++) {
        if (t + 2 < 16) {
            flash_issue((t + 2) * 128, sb + ((t + 2) % 3) * 32768, kbase, tid);
        }
        cp_commit();
        cp_wait<2>();
        __syncthreads();

        const uint32_t ks_base = sb + (t % 3) * 32768;
        const uint32_t vs_base = ks_base + 16384;

        // ---- S = Q K^T (single fp16; ks outer for long acc chains) ----
        float sf[16][4];
#pragma unroll
        for (int nt = 0; nt < 16; nt++)
#pragma unroll
            for (int e = 0; e < 4; e++) sf[nt][e] = 0.0f;

#pragma unroll
        for (int ks = 0; ks < 4; ks++) {
#pragma unroll
            for (int nt = 0; nt < 16; nt++) {
                int row = nt * 8 + (lane & 7);
                int ch = (2 * ks + ((lane >> 3) & 1)) ^ (row & 7);
                uint32_t ad = ks_base + row * 128 + (ch << 4);
                uint32_t kf[2];
                ldsm_x2(kf, ad);
                mma16816(sf[nt], qh[ks], kf);
            }
        }

        // ---- online softmax ----
        {
            float mx0 = sf[0][0], mx1 = sf[0][2];
#pragma unroll
            for (int nt = 0; nt < 16; nt++) {
                mx0 = fmaxf(mx0, fmaxf(sf[nt][0], sf[nt][1]));
                mx1 = fmaxf(mx1, fmaxf(sf[nt][2], sf[nt][3]));
            }
            mx0 = fmaxf(mx0, __shfl_xor_sync(0xffffffffu, mx0, 1));
            mx0 = fmaxf(mx0, __shfl_xor_sync(0xffffffffu, mx0, 2));
            mx1 = fmaxf(mx1, __shfl_xor_sync(0xffffffffu, mx1, 1));
            mx1 = fmaxf(mx1, __shfl_xor_sync(0xffffffffu, mx1, 2));
            float mn0 = fmaxf(mr[0], mx0), mn1 = fmaxf(mr[1], mx1);
            float c0 = __expf(mr[0] - mn0), c1 = __expf(mr[1] - mn1);
            float s0 = 0.0f, s1 = 0.0f;
#pragma unroll
            for (int nt = 0; nt < 16; nt++) {
                sf[nt][0] = __expf(sf[nt][0] - mn0);
                sf[nt][1] = __expf(sf[nt][1] - mn0);
                sf[nt][2] = __expf(sf[nt][2] - mn1);
                sf[nt][3] = __expf(sf[nt][3] - mn1);
                s0 += sf[nt][0] + sf[nt][1];
                s1 += sf[nt][2] + sf[nt][3];
            }
            s0 += __shfl_xor_sync(0xffffffffu, s0, 1);
            s0 += __shfl_xor_sync(0xffffffffu, s0, 2);
            s1 += __shfl_xor_sync(0xffffffffu, s1, 1);
            s1 += __shfl_xor_sync(0xffffffffu, s1, 2);
            lr[0] = lr[0] * c0 + s0;
            lr[1] = lr[1] * c1 + s1;
            mr[0] = mn0; mr[1] = mn1;
#pragma unroll
            for (int dt = 0; dt < 8; dt++) {
                o[dt][0] *= c0; o[dt][1] *= c0;
                o[dt][2] *= c1; o[dt][3] *= c1;
            }
        }

        // ---- O += P V (single fp16; V frags via ldmatrix.trans) ----
#pragma unroll
        for (int js = 0; js < 8; js++) {
            uint32_t ph4[4];
#pragma unroll
            for (int r = 0; r < 4; r++) {
                int tt = 2 * js + (r >> 1);
                int ci = (r & 1) * 2;
                ph4[r] = pack2h(sf[tt][ci], sf[tt][ci + 1]);
            }
            int vrow = js * 16 + (lane & 15);
#pragma unroll
            for (int dt = 0; dt < 8; dt++) {
                int ch = dt ^ (vrow & 7);
                uint32_t ad = vs_base + vrow * 128 + (ch << 4);
                uint32_t vf[2];
                ldsm_x2_trans(vf, ad);
                mma16816(o[dt], ph4, vf);
            }
        }
        __syncthreads();
    }

    // ---- epilogue: normalize, fp16 store to g_ao ----
    float i0 = 1.0f / lr[0], i1 = 1.0f / lr[1];
    int s0r = qb + wq * 16 + gr;
    int s1r = s0r + 8;
#pragma unroll
    for (int dt = 0; dt < 8; dt++) {
        size_t offA = ((size_t)(b * S_ + s0r)) * D_ + h * 64 + dt * 8 + gc;
        size_t offB = ((size_t)(b * S_ + s1r)) * D_ + h * 64 + dt * 8 + gc;
        *(uint32_t*)(g_ao + offA) = pack2h(o[dt][0] * i0, o[dt][1] * i0);
        *(uint32_t*)(g_ao + offB) = pack2h(o[dt][2] * i1, o[dt][3] * i1);
    }
}

// ---------------------------------------------------------------------------
// Launch  (gemm<0> stays 4th: the profiler captures the 4th launch)
// ---------------------------------------------------------------------------
extern "C" void kernel_launch(void* const* d_in, const int* in_sizes, int n_in,
                              void* d_out, int out_size) {
    const float* x      = (const float*)d_in[0];
    const int*   p      = (const int*)d_in[1];
    const float* Wqkv_w = (const float*)d_in[2];
    const float* Wqkv_b = (const float*)d_in[3];
    const float* Wo_w   = (const float*)d_in[4];
    const float* Wo_b   = (const float*)d_in[5];
    float* out = (float*)d_out;

    cudaFuncSetAttribute(flash_mma_kernel,
                         cudaFuncAttributeMaxDynamicSharedMemorySize, FLASH_SMEM);
    cudaFuncSetAttribute(tc_gemm_kernel<0>,
                         cudaFuncAttributeMaxDynamicSharedMemorySize, TCG_SMEM);
    cudaFuncSetAttribute(tc_gemm_kernel<1>,
                         cudaFuncAttributeMaxDynamicSharedMemorySize, TCG_SMEM);

    __half *x16, *wq, *ao, *wo;
    cudaGetSymbolAddress((void**)&x16, g_x16);
    cudaGetSymbolAddress((void**)&wq,  g_wq);
    cudaGetSymbolAddress((void**)&ao,  g_ao);
    cudaGetSymbolAddress((void**)&wo,  g_wo);

    // 1-3. input conversions + freqs
    convert_single_kernel<<<(B_ * S_ * D_) / 1024, 256>>>(x, x16);
    convert_single_kernel<<<(3 * D_ * D_) / 1024, 256>>>(Wqkv_w, wq);
    prep_freqs_kernel<<<1, 32>>>();

    // 4. QKV projection -> g_q/g_k fp32, g_vh fp16
    tc_gemm_kernel<0><<<dim3(3 * D_ / 128, (B_ * S_) / 128), 256, TCG_SMEM>>>(
        x16, wq, Wqkv_b, nullptr, 3 * D_);

    // 5. RoPE + fp16 conversion
    rope_split_kernel<<<(B_ * H_ * S_ * 32) / 256, 256>>>(p);

    // 6. Flash attention -> g_ao fp16
    flash_mma_kernel<<<dim3(S_ / 128, H_, B_), 256, FLASH_SMEM>>>();

    // 7-8. Wo conversion + output projection
    convert_single_kernel<<<(D_ * D_) / 1024, 256>>>(Wo_w, wo);
    tc_gemm_kernel<1><<<dim3(D_ / 128, (B_ * S_) / 128), 256, TCG_SMEM>>>(
        ao, wo, Wo_b, out, D_);
}